// round 1
// baseline (speedup 1.0000x reference)
#include <cuda_runtime.h>

// Static problem shapes (from setup_inputs)
#define BATCH 8
#define SEQ   2048
#define DIM   768
#define ROWS  (BATCH * SEQ)       // 16384
#define TEMP_INV (1.0f / 0.07f)

// ---------------------------------------------------------------------------
// Device-global scratch (no runtime allocation allowed)
// ---------------------------------------------------------------------------
__device__ float g_vp[BATCH * SEQ * DIM];            // 50.3 MB
__device__ float g_lp[BATCH * SEQ * DIM];            // 50.3 MB
__device__ float g_A[(size_t)BATCH * SEQ * SEQ];     // 134 MB  (sim / softmax / reused for out_pre)
__device__ float g_comb[BATCH * SEQ * 2 * DIM];      // 100.6 MB
__device__ float g_scale;                            // mean(claw)/TEMPERATURE

// ---------------------------------------------------------------------------
// claw mean -> g_scale  (single block, deterministic tree reduction)
// ---------------------------------------------------------------------------
__global__ void claw_mean_kernel(const float* __restrict__ claw) {
    __shared__ float red[1024];
    int tid = threadIdx.x;
    float s = 0.0f;
    for (int i = tid; i < DIM * DIM; i += 1024) s += claw[i];
    red[tid] = s;
    __syncthreads();
    for (int o = 512; o > 0; o >>= 1) {
        if (tid < o) red[tid] += red[tid + o];
        __syncthreads();
    }
    if (tid == 0) g_scale = (red[0] / (float)(DIM * DIM)) * TEMP_INV;
}

// ---------------------------------------------------------------------------
// Generic tiled SGEMM: C = alpha * op(A) @ op(B) + bias
//   TA=0: A(m,k)=A[m*lda+k]   TA=1: A(m,k)=A[k*lda+m]
//   TB=0: B(k,n)=B[k*ldb+n]   TB=1: B(k,n)=B[n*ldb+k]
// BM=BN=128, BK=8, 256 threads, 8x8 per-thread tile.
// Requires M%128==0, N%128==0, K%8==0, all ld%4==0 (true for all our shapes).
// alpha_ptr==nullptr -> alpha=1.  bias (length N) optional.
// blockIdx.z = batch; strides are per-batch element offsets.
// ---------------------------------------------------------------------------
template <int TA, int TB>
__global__ __launch_bounds__(256, 2)
void sgemm_kernel(const float* __restrict__ Ag, const float* __restrict__ Bg,
                  float* __restrict__ Cg,
                  int M, int N, int K, int lda, int ldb, int ldc,
                  long long sA, long long sB, long long sC,
                  const float* __restrict__ alpha_ptr,
                  const float* __restrict__ bias) {
    constexpr int BM = 128, BN = 128, BK = 8;
    __shared__ float As[BK][BM];
    __shared__ float Bs[BK][BN];

    const float* A = Ag + (long long)blockIdx.z * sA;
    const float* B = Bg + (long long)blockIdx.z * sB;
    float*       C = Cg + (long long)blockIdx.z * sC;

    const int tid  = threadIdx.x;
    const int tx   = tid & 15;       // 0..15 (cols)
    const int ty   = tid >> 4;       // 0..15 (rows)
    const int row0 = blockIdx.y * BM;
    const int col0 = blockIdx.x * BN;

    float acc[8][8] = {};

    for (int k0 = 0; k0 < K; k0 += BK) {
        // ---- load A tile into As[k][m] ----
        if (TA == 0) {
            int am = tid >> 1, ak = (tid & 1) * 4;
            float4 v = *reinterpret_cast<const float4*>(
                &A[(long long)(row0 + am) * lda + k0 + ak]);
            As[ak + 0][am] = v.x; As[ak + 1][am] = v.y;
            As[ak + 2][am] = v.z; As[ak + 3][am] = v.w;
        } else {
            int ak = tid >> 5, am = (tid & 31) * 4;
            float4 v = *reinterpret_cast<const float4*>(
                &A[(long long)(k0 + ak) * lda + row0 + am]);
            *reinterpret_cast<float4*>(&As[ak][am]) = v;
        }
        // ---- load B tile into Bs[k][n] ----
        if (TB == 0) {
            int bk = tid >> 5, bn = (tid & 31) * 4;
            float4 v = *reinterpret_cast<const float4*>(
                &B[(long long)(k0 + bk) * ldb + col0 + bn]);
            *reinterpret_cast<float4*>(&Bs[bk][bn]) = v;
        } else {
            int bn = tid >> 1, bk = (tid & 1) * 4;
            float4 v = *reinterpret_cast<const float4*>(
                &B[(long long)(col0 + bn) * ldb + k0 + bk]);
            Bs[bk + 0][bn] = v.x; Bs[bk + 1][bn] = v.y;
            Bs[bk + 2][bn] = v.z; Bs[bk + 3][bn] = v.w;
        }
        __syncthreads();

        #pragma unroll
        for (int kk = 0; kk < BK; kk++) {
            float ar[8], br[8];
            #pragma unroll
            for (int i = 0; i < 8; i++) ar[i] = As[kk][ty * 8 + i];
            #pragma unroll
            for (int j = 0; j < 8; j++) br[j] = Bs[kk][tx * 8 + j];
            #pragma unroll
            for (int i = 0; i < 8; i++)
                #pragma unroll
                for (int j = 0; j < 8; j++)
                    acc[i][j] += ar[i] * br[j];
        }
        __syncthreads();
    }

    const float alpha = alpha_ptr ? *alpha_ptr : 1.0f;
    #pragma unroll
    for (int i = 0; i < 8; i++) {
        long long r = row0 + ty * 8 + i;
        #pragma unroll
        for (int j = 0; j < 8; j += 4) {
            int c = col0 + tx * 8 + j;
            float4 v;
            v.x = acc[i][j + 0] * alpha;
            v.y = acc[i][j + 1] * alpha;
            v.z = acc[i][j + 2] * alpha;
            v.w = acc[i][j + 3] * alpha;
            if (bias) {
                v.x += bias[c + 0]; v.y += bias[c + 1];
                v.z += bias[c + 2]; v.w += bias[c + 3];
            }
            *reinterpret_cast<float4*>(&C[r * ldc + c]) = v;
        }
    }
}

// ---------------------------------------------------------------------------
// LayerNorm (+ReLU) over last dim = 768. One block (256 thr) per row.
// Y = relu((x - mean) * rsqrt(var + eps) * g + beta). In-place safe.
// ---------------------------------------------------------------------------
__global__ void ln_relu_kernel(const float* __restrict__ X, float* __restrict__ Y,
                               const float* __restrict__ g,
                               const float* __restrict__ beta) {
    __shared__ float red[256];
    const int tid = threadIdx.x;
    const float* x = X + (long long)blockIdx.x * DIM;
    float*       y = Y + (long long)blockIdx.x * DIM;

    float v0 = x[tid], v1 = x[tid + 256], v2 = x[tid + 512];

    red[tid] = v0 + v1 + v2;
    __syncthreads();
    for (int o = 128; o > 0; o >>= 1) {
        if (tid < o) red[tid] += red[tid + o];
        __syncthreads();
    }
    const float m = red[0] * (1.0f / DIM);
    __syncthreads();

    float d0 = v0 - m, d1 = v1 - m, d2 = v2 - m;
    red[tid] = d0 * d0 + d1 * d1 + d2 * d2;
    __syncthreads();
    for (int o = 128; o > 0; o >>= 1) {
        if (tid < o) red[tid] += red[tid + o];
        __syncthreads();
    }
    const float rs = rsqrtf(red[0] * (1.0f / DIM) + 1e-5f);

    y[tid]       = fmaxf(0.0f, d0 * rs * g[tid]       + beta[tid]);
    y[tid + 256] = fmaxf(0.0f, d1 * rs * g[tid + 256] + beta[tid + 256]);
    y[tid + 512] = fmaxf(0.0f, d2 * rs * g[tid + 512] + beta[tid + 512]);
}

// ---------------------------------------------------------------------------
// Row softmax over width 2048, in place. One block (256 thr) per row.
// ---------------------------------------------------------------------------
__global__ void softmax_kernel(float* __restrict__ A) {
    __shared__ float red[256];
    const int tid = threadIdx.x;
    float* x = A + (long long)blockIdx.x * SEQ;

    float4 a = *reinterpret_cast<const float4*>(&x[tid * 8]);
    float4 b = *reinterpret_cast<const float4*>(&x[tid * 8 + 4]);

    float mx = fmaxf(fmaxf(fmaxf(a.x, a.y), fmaxf(a.z, a.w)),
                     fmaxf(fmaxf(b.x, b.y), fmaxf(b.z, b.w)));
    red[tid] = mx;
    __syncthreads();
    for (int o = 128; o > 0; o >>= 1) {
        if (tid < o) red[tid] = fmaxf(red[tid], red[tid + o]);
        __syncthreads();
    }
    mx = red[0];
    __syncthreads();

    a.x = expf(a.x - mx); a.y = expf(a.y - mx);
    a.z = expf(a.z - mx); a.w = expf(a.w - mx);
    b.x = expf(b.x - mx); b.y = expf(b.y - mx);
    b.z = expf(b.z - mx); b.w = expf(b.w - mx);

    red[tid] = a.x + a.y + a.z + a.w + b.x + b.y + b.z + b.w;
    __syncthreads();
    for (int o = 128; o > 0; o >>= 1) {
        if (tid < o) red[tid] += red[tid + o];
        __syncthreads();
    }
    const float inv = 1.0f / red[0];

    a.x *= inv; a.y *= inv; a.z *= inv; a.w *= inv;
    b.x *= inv; b.y *= inv; b.z *= inv; b.w *= inv;
    *reinterpret_cast<float4*>(&x[tid * 8])     = a;
    *reinterpret_cast<float4*>(&x[tid * 8 + 4]) = b;
}

// ---------------------------------------------------------------------------
// Launch
// ---------------------------------------------------------------------------
extern "C" void kernel_launch(void* const* d_in, const int* in_sizes, int n_in,
                              void* d_out, int out_size) {
    const float* vis   = (const float*)d_in[0];
    const float* lang  = (const float*)d_in[1];
    const float* vW    = (const float*)d_in[2];
    const float* vb    = (const float*)d_in[3];
    const float* vg    = (const float*)d_in[4];
    const float* vbeta = (const float*)d_in[5];
    const float* lW    = (const float*)d_in[6];
    const float* lb    = (const float*)d_in[7];
    const float* lg    = (const float*)d_in[8];
    const float* lbeta = (const float*)d_in[9];
    const float* claw  = (const float*)d_in[10];
    const float* oW    = (const float*)d_in[11];
    const float* ob    = (const float*)d_in[12];
    const float* og    = (const float*)d_in[13];
    const float* obeta = (const float*)d_in[14];
    float* out = (float*)d_out;

    float *vp, *lp, *Am, *comb, *scale;
    cudaGetSymbolAddress((void**)&vp,    g_vp);
    cudaGetSymbolAddress((void**)&lp,    g_lp);
    cudaGetSymbolAddress((void**)&Am,    g_A);
    cudaGetSymbolAddress((void**)&comb,  g_comb);
    cudaGetSymbolAddress((void**)&scale, g_scale);

    // scale = mean(claw) / T
    claw_mean_kernel<<<1, 1024>>>(claw);

    // vp_pre = vision @ vW + vb   [16384,768]
    sgemm_kernel<0, 0><<<dim3(DIM / 128, ROWS / 128, 1), 256>>>(
        vis, vW, vp, ROWS, DIM, DIM, DIM, DIM, DIM, 0, 0, 0, nullptr, vb);
    // lp_pre = language @ lW + lb
    sgemm_kernel<0, 0><<<dim3(DIM / 128, ROWS / 128, 1), 256>>>(
        lang, lW, lp, ROWS, DIM, DIM, DIM, DIM, DIM, 0, 0, 0, nullptr, lb);

    // LN + ReLU (in place)
    ln_relu_kernel<<<ROWS, 256>>>(vp, vp, vg, vbeta);
    ln_relu_kernel<<<ROWS, 256>>>(lp, lp, lg, lbeta);

    // sim[b] = (vp[b] @ lp[b]^T) * scale   [8][2048,2048]
    sgemm_kernel<0, 1><<<dim3(SEQ / 128, SEQ / 128, BATCH), 256>>>(
        vp, lp, Am, SEQ, SEQ, DIM, DIM, DIM, SEQ,
        (long long)SEQ * DIM, (long long)SEQ * DIM, (long long)SEQ * SEQ,
        scale, nullptr);

    // A = softmax(sim) row-wise
    softmax_kernel<<<BATCH * SEQ, 256>>>(Am);

    // aligned_vision[b] = A[b] @ vp[b]  -> comb[:, 0:768]
    sgemm_kernel<0, 0><<<dim3(DIM / 128, SEQ / 128, BATCH), 256>>>(
        Am, vp, comb, SEQ, DIM, SEQ, SEQ, DIM, 2 * DIM,
        (long long)SEQ * SEQ, (long long)SEQ * DIM, (long long)SEQ * 2 * DIM,
        nullptr, nullptr);

    // aligned_language[b] = A[b]^T @ lp[b] -> comb[:, 768:1536]
    sgemm_kernel<1, 0><<<dim3(DIM / 128, SEQ / 128, BATCH), 256>>>(
        Am, lp, comb + DIM, SEQ, DIM, SEQ, SEQ, DIM, 2 * DIM,
        (long long)SEQ * SEQ, (long long)SEQ * DIM, (long long)SEQ * 2 * DIM,
        nullptr, nullptr);

    // out_pre = comb @ oW + ob  [16384,768]  (reuse g_A as scratch)
    sgemm_kernel<0, 0><<<dim3(DIM / 128, ROWS / 128, 1), 256>>>(
        comb, oW, Am, ROWS, DIM, 2 * DIM, 2 * DIM, DIM, DIM, 0, 0, 0,
        nullptr, ob);

    // final LN + ReLU -> out
    ln_relu_kernel<<<ROWS, 256>>>(Am, out, og, obeta);
}

// round 3
// speedup vs baseline: 2.6868x; 2.6868x over previous
#include <cuda_runtime.h>
#include <cstdint>

// Static problem shapes
#define BATCH 8
#define SEQ   2048
#define DIM   768
#define ROWS  (BATCH * SEQ)       // 16384
#define TEMP_INV (1.0f / 0.07f)

// ---------------------------------------------------------------------------
// Device-global scratch
// ---------------------------------------------------------------------------
__device__ float g_vp [ROWS * DIM];
__device__ float g_lp [ROWS * DIM];
__device__ float g_A  [(size_t)BATCH * SEQ * SEQ];
__device__ float g_At [(size_t)BATCH * SEQ * SEQ];
__device__ float g_comb[ROWS * 2 * DIM];
__device__ float g_vpT[ROWS * DIM];
__device__ float g_lpT[ROWS * DIM];
__device__ float g_vWT[DIM * DIM];
__device__ float g_lWT[DIM * DIM];
__device__ float g_oWT[2 * DIM * DIM];
__device__ float g_scale;

// ---------------------------------------------------------------------------
// tf32 mma.sync GEMM:  C[M,N] = alpha * A[M,K] @ BT[N,K]^T + bias
// CTA tile 128x128x16, 8 warps (2x4), warp tile 64x32.
// A row-major [M,K] (lda), BT row-major [N,K] (ldb), C row-major (ldc).
// Requires M%128==0, N%128==0, K%16==0, 16B-aligned rows.
// grid = (N/128, M/128, batch), 256 threads.
// ---------------------------------------------------------------------------
#define SMS 24   // smem row stride (floats): 96B, 16B-aligned, conflict-light

__device__ __forceinline__ uint32_t f2tf32(float f) {
    uint32_t u;
    asm("cvt.rna.tf32.f32 %0, %1;" : "=r"(u) : "f"(f));
    return u;
}

__device__ __forceinline__ void mma_tf32(float* c, const uint32_t* a, const uint32_t* b) {
    asm volatile(
        "mma.sync.aligned.m16n8k8.row.col.f32.tf32.tf32.f32 "
        "{%0,%1,%2,%3}, {%4,%5,%6,%7}, {%8,%9}, {%0,%1,%2,%3};"
        : "+f"(c[0]), "+f"(c[1]), "+f"(c[2]), "+f"(c[3])
        : "r"(a[0]), "r"(a[1]), "r"(a[2]), "r"(a[3]), "r"(b[0]), "r"(b[1]));
}

__device__ __forceinline__ void cp16(float* smem_dst, const float* gsrc) {
    uint32_t d;
    asm("{ .reg .u64 t; cvta.to.shared.u64 t, %1; cvt.u32.u64 %0, t; }" : "=r"(d) : "l"(smem_dst));
    asm volatile("cp.async.cg.shared.global [%0], [%1], 16;"
                 :: "r"(d), "l"(__cvta_generic_to_global(gsrc)) : "memory");
}

__global__ __launch_bounds__(256, 1)
void tf32_gemm(const float* __restrict__ Ag, const float* __restrict__ Bg,
               float* __restrict__ Cg,
               int lda, int ldb, int ldc, int K,
               long long sA, long long sB, long long sC,
               const float* __restrict__ alpha_ptr, const float* __restrict__ bias) {
    __shared__ float As[2][128][SMS];
    __shared__ float Bs[2][128][SMS];

    const int tid  = threadIdx.x;
    const int wid  = tid >> 5;
    const int lane = tid & 31;
    const int gid  = lane >> 2;       // 0..7
    const int t4   = lane & 3;        // 0..3
    const int warp_m = (wid >> 2) * 64;   // 0 or 64
    const int warp_n = (wid & 3) * 32;    // 0,32,64,96

    const float* A = Ag + (long long)blockIdx.z * sA + (long long)blockIdx.y * 128 * lda;
    const float* B = Bg + (long long)blockIdx.z * sB + (long long)blockIdx.x * 128 * ldb;

    // per-thread load coords: 512 16B-chunks per tile, 2 per thread
    const int r0 = tid >> 1, c0 = (tid & 1) * 8;            // chunk set A: rows 0..127, col 0/8
    // simpler: chunk = tid + i*256 -> row = chunk>>2, c = (chunk&3)*4

    float acc[4][4][4];
    #pragma unroll
    for (int i = 0; i < 4; i++)
        #pragma unroll
        for (int j = 0; j < 4; j++)
            #pragma unroll
            for (int r = 0; r < 4; r++) acc[i][j][r] = 0.0f;
    (void)r0; (void)c0;

    const int KT = K >> 4;

    // prologue: tile 0 into buf 0
    #pragma unroll
    for (int i = 0; i < 2; i++) {
        int chunk = tid + i * 256;
        int row = chunk >> 2, c = (chunk & 3) * 4;
        cp16(&As[0][row][c], &A[(long long)row * lda + c]);
        cp16(&Bs[0][row][c], &B[(long long)row * ldb + c]);
    }
    asm volatile("cp.async.commit_group;" ::: "memory");

    int buf = 0;
    for (int kt = 0; kt < KT; kt++) {
        if (kt + 1 < KT) {
            const float* a = A + ((kt + 1) << 4);
            const float* b = B + ((kt + 1) << 4);
            #pragma unroll
            for (int i = 0; i < 2; i++) {
                int chunk = tid + i * 256;
                int row = chunk >> 2, c = (chunk & 3) * 4;
                cp16(&As[buf ^ 1][row][c], &a[(long long)row * lda + c]);
                cp16(&Bs[buf ^ 1][row][c], &b[(long long)row * ldb + c]);
            }
            asm volatile("cp.async.commit_group;" ::: "memory");
            asm volatile("cp.async.wait_group 1;" ::: "memory");
        } else {
            asm volatile("cp.async.wait_group 0;" ::: "memory");
        }
        __syncthreads();

        #pragma unroll
        for (int ks = 0; ks < 2; ks++) {
            const int k0 = ks * 8;
            uint32_t afr[4][4], bfr[4][2];
            #pragma unroll
            for (int mb = 0; mb < 4; mb++) {
                const float* p = &As[buf][warp_m + mb * 16 + gid][k0 + t4];
                afr[mb][0] = f2tf32(p[0]);
                afr[mb][1] = f2tf32(p[8 * SMS]);
                afr[mb][2] = f2tf32(p[4]);
                afr[mb][3] = f2tf32(p[8 * SMS + 4]);
            }
            #pragma unroll
            for (int nb = 0; nb < 4; nb++) {
                const float* p = &Bs[buf][warp_n + nb * 8 + gid][k0 + t4];
                bfr[nb][0] = f2tf32(p[0]);
                bfr[nb][1] = f2tf32(p[4]);
            }
            #pragma unroll
            for (int mb = 0; mb < 4; mb++)
                #pragma unroll
                for (int nb = 0; nb < 4; nb++)
                    mma_tf32(acc[mb][nb], afr[mb], bfr[nb]);
        }
        __syncthreads();
        buf ^= 1;
    }

    // epilogue
    const float alpha = alpha_ptr ? *alpha_ptr : 1.0f;
    float* C = Cg + (long long)blockIdx.z * sC + (long long)blockIdx.y * 128 * ldc
             + (long long)blockIdx.x * 128;
    const int colbase = blockIdx.x * 128;
    #pragma unroll
    for (int mb = 0; mb < 4; mb++) {
        const int row = warp_m + mb * 16 + gid;
        #pragma unroll
        for (int nb = 0; nb < 4; nb++) {
            const int col = warp_n + nb * 8 + 2 * t4;
            float bx = 0.0f, by = 0.0f;
            if (bias) { bx = bias[colbase + col]; by = bias[colbase + col + 1]; }
            float2 v0 = { acc[mb][nb][0] * alpha + bx, acc[mb][nb][1] * alpha + by };
            float2 v1 = { acc[mb][nb][2] * alpha + bx, acc[mb][nb][3] * alpha + by };
            *reinterpret_cast<float2*>(&C[(long long)row * ldc + col])       = v0;
            *reinterpret_cast<float2*>(&C[(long long)(row + 8) * ldc + col]) = v1;
        }
    }
}

// ---------------------------------------------------------------------------
// Tiled transpose: out[c][r] = in[r][c].  R%32==0, C%32==0.
// ---------------------------------------------------------------------------
__global__ void transpose_kernel(const float* __restrict__ in, float* __restrict__ out,
                                 int R, int C, long long sIn, long long sOut) {
    __shared__ float t[32][33];
    in  += (long long)blockIdx.z * sIn;
    out += (long long)blockIdx.z * sOut;
    int x  = blockIdx.x * 32 + threadIdx.x;
    int y0 = blockIdx.y * 32;
    #pragma unroll
    for (int i = threadIdx.y; i < 32; i += 8)
        t[i][threadIdx.x] = in[(long long)(y0 + i) * C + x];
    __syncthreads();
    int ox  = y0 + threadIdx.x;
    int oy0 = blockIdx.x * 32;
    #pragma unroll
    for (int i = threadIdx.y; i < 32; i += 8)
        out[(long long)(oy0 + i) * R + ox] = t[threadIdx.x][i];
}

// ---------------------------------------------------------------------------
// claw mean -> g_scale
// ---------------------------------------------------------------------------
__global__ void claw_mean_kernel(const float* __restrict__ claw) {
    __shared__ float red[1024];
    int tid = threadIdx.x;
    float s = 0.0f;
    for (int i = tid; i < DIM * DIM; i += 1024) s += claw[i];
    red[tid] = s;
    __syncthreads();
    for (int o = 512; o > 0; o >>= 1) {
        if (tid < o) red[tid] += red[tid + o];
        __syncthreads();
    }
    if (tid == 0) g_scale = (red[0] / (float)(DIM * DIM)) * TEMP_INV;
}

// ---------------------------------------------------------------------------
// LayerNorm (+ReLU) over last dim 768. One block (256) per row.
// ---------------------------------------------------------------------------
__global__ void ln_relu_kernel(const float* __restrict__ X, float* __restrict__ Y,
                               const float* __restrict__ g, const float* __restrict__ beta) {
    __shared__ float red[256];
    const int tid = threadIdx.x;
    const float* x = X + (long long)blockIdx.x * DIM;
    float*       y = Y + (long long)blockIdx.x * DIM;

    float v0 = x[tid], v1 = x[tid + 256], v2 = x[tid + 512];
    red[tid] = v0 + v1 + v2;
    __syncthreads();
    for (int o = 128; o > 0; o >>= 1) { if (tid < o) red[tid] += red[tid + o]; __syncthreads(); }
    const float m = red[0] * (1.0f / DIM);
    __syncthreads();
    float d0 = v0 - m, d1 = v1 - m, d2 = v2 - m;
    red[tid] = d0 * d0 + d1 * d1 + d2 * d2;
    __syncthreads();
    for (int o = 128; o > 0; o >>= 1) { if (tid < o) red[tid] += red[tid + o]; __syncthreads(); }
    const float rs = rsqrtf(red[0] * (1.0f / DIM) + 1e-5f);
    y[tid]       = fmaxf(0.0f, d0 * rs * g[tid]       + beta[tid]);
    y[tid + 256] = fmaxf(0.0f, d1 * rs * g[tid + 256] + beta[tid + 256]);
    y[tid + 512] = fmaxf(0.0f, d2 * rs * g[tid + 512] + beta[tid + 512]);
}

// ---------------------------------------------------------------------------
// Row softmax over 2048, in place. One block (256) per row.
// ---------------------------------------------------------------------------
__global__ void softmax_kernel(float* __restrict__ A) {
    __shared__ float red[256];
    const int tid = threadIdx.x;
    float* x = A + (long long)blockIdx.x * SEQ;
    float4 a = *reinterpret_cast<const float4*>(&x[tid * 8]);
    float4 b = *reinterpret_cast<const float4*>(&x[tid * 8 + 4]);
    float mx = fmaxf(fmaxf(fmaxf(a.x, a.y), fmaxf(a.z, a.w)),
                     fmaxf(fmaxf(b.x, b.y), fmaxf(b.z, b.w)));
    red[tid] = mx;
    __syncthreads();
    for (int o = 128; o > 0; o >>= 1) { if (tid < o) red[tid] = fmaxf(red[tid], red[tid + o]); __syncthreads(); }
    mx = red[0];
    __syncthreads();
    a.x = expf(a.x - mx); a.y = expf(a.y - mx); a.z = expf(a.z - mx); a.w = expf(a.w - mx);
    b.x = expf(b.x - mx); b.y = expf(b.y - mx); b.z = expf(b.z - mx); b.w = expf(b.w - mx);
    red[tid] = a.x + a.y + a.z + a.w + b.x + b.y + b.z + b.w;
    __syncthreads();
    for (int o = 128; o > 0; o >>= 1) { if (tid < o) red[tid] += red[tid + o]; __syncthreads(); }
    const float inv = 1.0f / red[0];
    a.x *= inv; a.y *= inv; a.z *= inv; a.w *= inv;
    b.x *= inv; b.y *= inv; b.z *= inv; b.w *= inv;
    *reinterpret_cast<float4*>(&x[tid * 8])     = a;
    *reinterpret_cast<float4*>(&x[tid * 8 + 4]) = b;
}

// ---------------------------------------------------------------------------
// Launch
// ---------------------------------------------------------------------------
extern "C" void kernel_launch(void* const* d_in, const int* in_sizes, int n_in,
                              void* d_out, int out_size) {
    const float* vis   = (const float*)d_in[0];
    const float* lang  = (const float*)d_in[1];
    const float* vW    = (const float*)d_in[2];
    const float* vb    = (const float*)d_in[3];
    const float* vg    = (const float*)d_in[4];
    const float* vbeta = (const float*)d_in[5];
    const float* lW    = (const float*)d_in[6];
    const float* lb    = (const float*)d_in[7];
    const float* lg    = (const float*)d_in[8];
    const float* lbeta = (const float*)d_in[9];
    const float* claw  = (const float*)d_in[10];
    const float* oW    = (const float*)d_in[11];
    const float* ob    = (const float*)d_in[12];
    const float* og    = (const float*)d_in[13];
    const float* obeta = (const float*)d_in[14];
    float* out = (float*)d_out;

    float *vp, *lp, *Am, *At, *comb, *vpT, *lpT, *vWT, *lWT, *oWT, *scale;
    cudaGetSymbolAddress((void**)&vp,    g_vp);
    cudaGetSymbolAddress((void**)&lp,    g_lp);
    cudaGetSymbolAddress((void**)&Am,    g_A);
    cudaGetSymbolAddress((void**)&At,    g_At);
    cudaGetSymbolAddress((void**)&comb,  g_comb);
    cudaGetSymbolAddress((void**)&vpT,   g_vpT);
    cudaGetSymbolAddress((void**)&lpT,   g_lpT);
    cudaGetSymbolAddress((void**)&vWT,   g_vWT);
    cudaGetSymbolAddress((void**)&lWT,   g_lWT);
    cudaGetSymbolAddress((void**)&oWT,   g_oWT);
    cudaGetSymbolAddress((void**)&scale, g_scale);

    const long long SD = (long long)SEQ * DIM;
    const long long SS = (long long)SEQ * SEQ;
    const long long SC = (long long)SEQ * 2 * DIM;

    // scale = mean(claw)/T
    claw_mean_kernel<<<1, 1024>>>(claw);

    // weight transposes: W[K,N] -> WT[N,K]
    transpose_kernel<<<dim3(DIM / 32, DIM / 32, 1), dim3(32, 8)>>>(vW, vWT, DIM, DIM, 0, 0);
    transpose_kernel<<<dim3(DIM / 32, DIM / 32, 1), dim3(32, 8)>>>(lW, lWT, DIM, DIM, 0, 0);
    transpose_kernel<<<dim3(DIM / 32, (2 * DIM) / 32, 1), dim3(32, 8)>>>(oW, oWT, 2 * DIM, DIM, 0, 0);

    // vp_pre = vis @ vW + vb ; lp_pre = lang @ lW + lb
    tf32_gemm<<<dim3(DIM / 128, ROWS / 128, 1), 256>>>(
        vis, vWT, vp, DIM, DIM, DIM, DIM, 0, 0, 0, nullptr, vb);
    tf32_gemm<<<dim3(DIM / 128, ROWS / 128, 1), 256>>>(
        lang, lWT, lp, DIM, DIM, DIM, DIM, 0, 0, 0, nullptr, lb);

    // LN + ReLU (in place)
    ln_relu_kernel<<<ROWS, 256>>>(vp, vp, vg, vbeta);
    ln_relu_kernel<<<ROWS, 256>>>(lp, lp, lg, lbeta);

    // transposed projections: [S,D] -> [D,S] per batch
    transpose_kernel<<<dim3(DIM / 32, SEQ / 32, BATCH), dim3(32, 8)>>>(vp, vpT, SEQ, DIM, SD, SD);
    transpose_kernel<<<dim3(DIM / 32, SEQ / 32, BATCH), dim3(32, 8)>>>(lp, lpT, SEQ, DIM, SD, SD);

    // sim[b] = (vp[b] @ lp[b]^T) * scale
    tf32_gemm<<<dim3(SEQ / 128, SEQ / 128, BATCH), 256>>>(
        vp, lp, Am, DIM, DIM, SEQ, DIM, SD, SD, SS, scale, nullptr);

    // A = softmax(sim)
    softmax_kernel<<<BATCH * SEQ, 256>>>(Am);

    // At[b] = A[b]^T
    transpose_kernel<<<dim3(SEQ / 32, SEQ / 32, BATCH), dim3(32, 8)>>>(Am, At, SEQ, SEQ, SS, SS);

    // aligned_vision[b] = A[b] @ vp[b]
    tf32_gemm<<<dim3(DIM / 128, SEQ / 128, BATCH), 256>>>(
        Am, vpT, comb, SEQ, SEQ, 2 * DIM, SEQ, SS, SD, SC, nullptr, nullptr);

    // aligned_language[b] = A[b]^T @ lp[b]
    tf32_gemm<<<dim3(DIM / 128, SEQ / 128, BATCH), 256>>>(
        At, lpT, comb + DIM, SEQ, SEQ, 2 * DIM, SEQ, SS, SD, SC, nullptr, nullptr);

    // out_pre = comb @ oW + ob  (reuse vp)
    tf32_gemm<<<dim3(DIM / 128, ROWS / 128, 1), 256>>>(
        comb, oWT, vp, 2 * DIM, 2 * DIM, DIM, 2 * DIM, 0, 0, 0, nullptr, ob);

    // final LN + ReLU
    ln_relu_kernel<<<ROWS, 256>>>(vp, out, og, obeta);
}

// round 4
// speedup vs baseline: 4.9532x; 1.8435x over previous
#include <cuda_runtime.h>
#include <cuda_fp16.h>
#include <cstdint>

// Static problem shapes
#define BATCH 8
#define SEQ   2048
#define DIM   768
#define ROWS  (BATCH * SEQ)       // 16384
#define TEMP_INV (1.0f / 0.07f)

// ---------------------------------------------------------------------------
// Device-global scratch
// ---------------------------------------------------------------------------
__device__ float  g_A[(size_t)BATCH * SEQ * SEQ];   // f32: proj tmps / sim / out_pre
__device__ __half g_visH [ROWS * DIM];
__device__ __half g_langH[ROWS * DIM];
__device__ __half g_vpH  [ROWS * DIM];
__device__ __half g_lpH  [ROWS * DIM];
__device__ __half g_vpTH [ROWS * DIM];
__device__ __half g_lpTH [ROWS * DIM];
__device__ __half g_AmH[(size_t)BATCH * SEQ * SEQ];
__device__ __half g_AtH[(size_t)BATCH * SEQ * SEQ];
__device__ __half g_combH[ROWS * 2 * DIM];
__device__ __half g_vWTH[DIM * DIM];
__device__ __half g_lWTH[DIM * DIM];
__device__ __half g_oWTH[2 * DIM * DIM];
__device__ float  g_scale;

// ---------------------------------------------------------------------------
// PTX helpers
// ---------------------------------------------------------------------------
__device__ __forceinline__ uint32_t smem_u32(const void* p) {
    uint32_t a;
    asm("{ .reg .u64 t; cvta.to.shared.u64 t, %1; cvt.u32.u64 %0, t; }" : "=r"(a) : "l"(p));
    return a;
}
__device__ __forceinline__ void cp16(void* sdst, const void* gsrc) {
    asm volatile("cp.async.cg.shared.global [%0], [%1], 16;"
                 :: "r"(smem_u32(sdst)), "l"(__cvta_generic_to_global(gsrc)) : "memory");
}
__device__ __forceinline__ void ldsm4(uint32_t* r, uint32_t addr) {
    asm volatile("ldmatrix.sync.aligned.m8n8.x4.shared.b16 {%0,%1,%2,%3}, [%4];"
                 : "=r"(r[0]), "=r"(r[1]), "=r"(r[2]), "=r"(r[3]) : "r"(addr));
}
__device__ __forceinline__ void mma16816(float* c, const uint32_t* a, const uint32_t* b) {
    asm volatile(
        "mma.sync.aligned.m16n8k16.row.col.f32.f16.f16.f32 "
        "{%0,%1,%2,%3}, {%4,%5,%6,%7}, {%8,%9}, {%0,%1,%2,%3};"
        : "+f"(c[0]), "+f"(c[1]), "+f"(c[2]), "+f"(c[3])
        : "r"(a[0]), "r"(a[1]), "r"(a[2]), "r"(a[3]), "r"(b[0]), "r"(b[1]));
}
__device__ __forceinline__ void store2(float* p, float x, float y) {
    *reinterpret_cast<float2*>(p) = make_float2(x, y);
}
__device__ __forceinline__ void store2(__half* p, float x, float y) {
    *reinterpret_cast<__half2*>(p) = __floats2half2_rn(x, y);
}

// ---------------------------------------------------------------------------
// fp16 mma.sync GEMM: C[M,N] = alpha * A[M,K] @ BT[N,K]^T + bias
// CTA 128x128x32(halves), 8 warps (2x4), warp tile 64x32, ldmatrix fragments.
// A/BT row-major half; C row-major OUT (float or half).
// Requires M%128==0, N%128==0, K%32==0, 16B-aligned rows.
// grid = (N/128, M/128, batch), 256 threads.
// ---------------------------------------------------------------------------
#define SMSH 40   // smem row stride in halves (80B) -> conflict-free LDSM

template <typename OUT>
__global__ __launch_bounds__(256, 2)
void h_gemm(const __half* __restrict__ Ag, const __half* __restrict__ Bg,
            OUT* __restrict__ Cg,
            int lda, int ldb, int ldc, int K,
            long long sA, long long sB, long long sC,
            const float* __restrict__ alpha_ptr, const float* __restrict__ bias) {
    __shared__ __half As[2][128][SMSH];
    __shared__ __half Bs[2][128][SMSH];

    const int tid  = threadIdx.x;
    const int wid  = tid >> 5;
    const int lane = tid & 31;
    const int gid  = lane >> 2;
    const int t4   = lane & 3;
    const int warp_m = (wid >> 2) * 64;
    const int warp_n = (wid & 3) * 32;

    const __half* A = Ag + (long long)blockIdx.z * sA + (long long)blockIdx.y * 128 * lda;
    const __half* B = Bg + (long long)blockIdx.z * sB + (long long)blockIdx.x * 128 * ldb;

    // ldmatrix per-lane coords (within tile)
    const int arow = warp_m + (lane & 7) + 8 * ((lane >> 3) & 1);
    const int acol = 8 * (lane >> 4);
    const int brow = warp_n + (lane & 7) + 8 * (lane >> 4);
    const int bcol = 8 * ((lane >> 3) & 1);
    uint32_t aBase[2] = { smem_u32(&As[0][arow][acol]), smem_u32(&As[1][arow][acol]) };
    uint32_t bBase[2] = { smem_u32(&Bs[0][brow][bcol]), smem_u32(&Bs[1][brow][bcol]) };

    float acc[4][4][4] = {};

    const int KT = K >> 5;   // 32 halves per k-tile

    // prologue: tile 0 into buf 0
    #pragma unroll
    for (int i = 0; i < 2; i++) {
        int chunk = tid + i * 256;                 // 512 chunks of 16B
        int row = chunk >> 2, c = (chunk & 3) * 8; // 8 halves per chunk
        cp16(&As[0][row][c], A + (long long)row * lda + c);
        cp16(&Bs[0][row][c], B + (long long)row * ldb + c);
    }
    asm volatile("cp.async.commit_group;" ::: "memory");

    int buf = 0;
    for (int kt = 0; kt < KT; kt++) {
        if (kt + 1 < KT) {
            const __half* a = A + (kt + 1) * 32;
            const __half* b = B + (kt + 1) * 32;
            #pragma unroll
            for (int i = 0; i < 2; i++) {
                int chunk = tid + i * 256;
                int row = chunk >> 2, c = (chunk & 3) * 8;
                cp16(&As[buf ^ 1][row][c], a + (long long)row * lda + c);
                cp16(&Bs[buf ^ 1][row][c], b + (long long)row * ldb + c);
            }
            asm volatile("cp.async.commit_group;" ::: "memory");
            asm volatile("cp.async.wait_group 1;" ::: "memory");
        } else {
            asm volatile("cp.async.wait_group 0;" ::: "memory");
        }
        __syncthreads();

        #pragma unroll
        for (int ks = 0; ks < 2; ks++) {
            const uint32_t koff = ks * 16 * 2;     // 16 halves = 32 bytes
            uint32_t afr[4][4], bfr[4][2], btmp[4];
            #pragma unroll
            for (int mb = 0; mb < 4; mb++)
                ldsm4(afr[mb], aBase[buf] + mb * 16 * SMSH * 2 + koff);
            ldsm4(btmp, bBase[buf] + koff);
            bfr[0][0] = btmp[0]; bfr[0][1] = btmp[1];
            bfr[1][0] = btmp[2]; bfr[1][1] = btmp[3];
            ldsm4(btmp, bBase[buf] + 16 * SMSH * 2 + koff);
            bfr[2][0] = btmp[0]; bfr[2][1] = btmp[1];
            bfr[3][0] = btmp[2]; bfr[3][1] = btmp[3];
            #pragma unroll
            for (int mb = 0; mb < 4; mb++)
                #pragma unroll
                for (int nb = 0; nb < 4; nb++)
                    mma16816(acc[mb][nb], afr[mb], bfr[nb]);
        }
        __syncthreads();
        buf ^= 1;
    }

    // epilogue
    const float alpha = alpha_ptr ? *alpha_ptr : 1.0f;
    OUT* C = Cg + (long long)blockIdx.z * sC + (long long)blockIdx.y * 128 * ldc
           + (long long)blockIdx.x * 128;
    const int colbase = blockIdx.x * 128;
    #pragma unroll
    for (int mb = 0; mb < 4; mb++) {
        const int row = warp_m + mb * 16 + gid;
        #pragma unroll
        for (int nb = 0; nb < 4; nb++) {
            const int col = warp_n + nb * 8 + 2 * t4;
            float bx = 0.0f, by = 0.0f;
            if (bias) { bx = bias[colbase + col]; by = bias[colbase + col + 1]; }
            store2(&C[(long long)row * ldc + col],
                   acc[mb][nb][0] * alpha + bx, acc[mb][nb][1] * alpha + by);
            store2(&C[(long long)(row + 8) * ldc + col],
                   acc[mb][nb][2] * alpha + bx, acc[mb][nb][3] * alpha + by);
        }
    }
}

// ---------------------------------------------------------------------------
// float -> half bulk convert
// ---------------------------------------------------------------------------
__global__ void f2h_kernel(const float* __restrict__ in, __half* __restrict__ out, int n4) {
    int i = blockIdx.x * blockDim.x + threadIdx.x;
    if (i < n4) {
        float4 v = reinterpret_cast<const float4*>(in)[i];
        __half2* o = reinterpret_cast<__half2*>(out);
        o[2 * i]     = __floats2half2_rn(v.x, v.y);
        o[2 * i + 1] = __floats2half2_rn(v.z, v.w);
    }
}

// ---------------------------------------------------------------------------
// Tiled transpose: out[c][r] = (TO)in[r][c].  R%32==0, C%32==0.
// ---------------------------------------------------------------------------
template <typename TI, typename TO>
__global__ void transpose_kernel(const TI* __restrict__ in, TO* __restrict__ out,
                                 int R, int C, long long sIn, long long sOut) {
    __shared__ float t[32][33];
    in  += (long long)blockIdx.z * sIn;
    out += (long long)blockIdx.z * sOut;
    int x  = blockIdx.x * 32 + threadIdx.x;
    int y0 = blockIdx.y * 32;
    #pragma unroll
    for (int i = threadIdx.y; i < 32; i += 8)
        t[i][threadIdx.x] = (float)in[(long long)(y0 + i) * C + x];
    __syncthreads();
    int ox  = y0 + threadIdx.x;
    int oy0 = blockIdx.x * 32;
    #pragma unroll
    for (int i = threadIdx.y; i < 32; i += 8)
        out[(long long)(oy0 + i) * R + ox] = (TO)t[threadIdx.x][i];
}

// ---------------------------------------------------------------------------
// claw mean -> g_scale
// ---------------------------------------------------------------------------
__global__ void claw_mean_kernel(const float* __restrict__ claw) {
    __shared__ float red[1024];
    int tid = threadIdx.x;
    float s = 0.0f;
    for (int i = tid; i < DIM * DIM; i += 1024) s += claw[i];
    red[tid] = s;
    __syncthreads();
    for (int o = 512; o > 0; o >>= 1) {
        if (tid < o) red[tid] += red[tid + o];
        __syncthreads();
    }
    if (tid == 0) g_scale = (red[0] / (float)(DIM * DIM)) * TEMP_INV;
}

// ---------------------------------------------------------------------------
// LayerNorm (+ReLU), last dim 768. One block (256) per row. f32 in, OUT out.
// ---------------------------------------------------------------------------
template <typename OUT>
__global__ void ln_relu_kernel(const float* __restrict__ X, OUT* __restrict__ Y,
                               const float* __restrict__ g, const float* __restrict__ beta) {
    __shared__ float red[256];
    const int tid = threadIdx.x;
    const float* x = X + (long long)blockIdx.x * DIM;
    OUT*         y = Y + (long long)blockIdx.x * DIM;

    float v0 = x[tid], v1 = x[tid + 256], v2 = x[tid + 512];
    red[tid] = v0 + v1 + v2;
    __syncthreads();
    for (int o = 128; o > 0; o >>= 1) { if (tid < o) red[tid] += red[tid + o]; __syncthreads(); }
    const float m = red[0] * (1.0f / DIM);
    __syncthreads();
    float d0 = v0 - m, d1 = v1 - m, d2 = v2 - m;
    red[tid] = d0 * d0 + d1 * d1 + d2 * d2;
    __syncthreads();
    for (int o = 128; o > 0; o >>= 1) { if (tid < o) red[tid] += red[tid + o]; __syncthreads(); }
    const float rs = rsqrtf(red[0] * (1.0f / DIM) + 1e-5f);
    y[tid]       = (OUT)fmaxf(0.0f, d0 * rs * g[tid]       + beta[tid]);
    y[tid + 256] = (OUT)fmaxf(0.0f, d1 * rs * g[tid + 256] + beta[tid + 256]);
    y[tid + 512] = (OUT)fmaxf(0.0f, d2 * rs * g[tid + 512] + beta[tid + 512]);
}

// ---------------------------------------------------------------------------
// Row softmax over 2048: f32 in -> half out. One block (256) per row.
// ---------------------------------------------------------------------------
__global__ void softmax_h_kernel(const float* __restrict__ X, __half* __restrict__ O) {
    __shared__ float red[256];
    const int tid = threadIdx.x;
    const float* x = X + (long long)blockIdx.x * SEQ;
    __half2*     o = reinterpret_cast<__half2*>(O + (long long)blockIdx.x * SEQ);

    float4 a = *reinterpret_cast<const float4*>(&x[tid * 8]);
    float4 b = *reinterpret_cast<const float4*>(&x[tid * 8 + 4]);
    float mx = fmaxf(fmaxf(fmaxf(a.x, a.y), fmaxf(a.z, a.w)),
                     fmaxf(fmaxf(b.x, b.y), fmaxf(b.z, b.w)));
    red[tid] = mx;
    __syncthreads();
    for (int s = 128; s > 0; s >>= 1) { if (tid < s) red[tid] = fmaxf(red[tid], red[tid + s]); __syncthreads(); }
    mx = red[0];
    __syncthreads();
    a.x = expf(a.x - mx); a.y = expf(a.y - mx); a.z = expf(a.z - mx); a.w = expf(a.w - mx);
    b.x = expf(b.x - mx); b.y = expf(b.y - mx); b.z = expf(b.z - mx); b.w = expf(b.w - mx);
    red[tid] = a.x + a.y + a.z + a.w + b.x + b.y + b.z + b.w;
    __syncthreads();
    for (int s = 128; s > 0; s >>= 1) { if (tid < s) red[tid] += red[tid + s]; __syncthreads(); }
    const float inv = 1.0f / red[0];
    o[tid * 4 + 0] = __floats2half2_rn(a.x * inv, a.y * inv);
    o[tid * 4 + 1] = __floats2half2_rn(a.z * inv, a.w * inv);
    o[tid * 4 + 2] = __floats2half2_rn(b.x * inv, b.y * inv);
    o[tid * 4 + 3] = __floats2half2_rn(b.z * inv, b.w * inv);
}

// ---------------------------------------------------------------------------
// Launch
// ---------------------------------------------------------------------------
extern "C" void kernel_launch(void* const* d_in, const int* in_sizes, int n_in,
                              void* d_out, int out_size) {
    const float* vis   = (const float*)d_in[0];
    const float* lang  = (const float*)d_in[1];
    const float* vW    = (const float*)d_in[2];
    const float* vb    = (const float*)d_in[3];
    const float* vg    = (const float*)d_in[4];
    const float* vbeta = (const float*)d_in[5];
    const float* lW    = (const float*)d_in[6];
    const float* lb    = (const float*)d_in[7];
    const float* lg    = (const float*)d_in[8];
    const float* lbeta = (const float*)d_in[9];
    const float* claw  = (const float*)d_in[10];
    const float* oW    = (const float*)d_in[11];
    const float* ob    = (const float*)d_in[12];
    const float* og    = (const float*)d_in[13];
    const float* obeta = (const float*)d_in[14];
    float* out = (float*)d_out;

    float  *Af, *scale;
    __half *visH, *langH, *vpH, *lpH, *vpTH, *lpTH, *AmH, *AtH, *combH, *vWTH, *lWTH, *oWTH;
    cudaGetSymbolAddress((void**)&Af,    g_A);
    cudaGetSymbolAddress((void**)&visH,  g_visH);
    cudaGetSymbolAddress((void**)&langH, g_langH);
    cudaGetSymbolAddress((void**)&vpH,   g_vpH);
    cudaGetSymbolAddress((void**)&lpH,   g_lpH);
    cudaGetSymbolAddress((void**)&vpTH,  g_vpTH);
    cudaGetSymbolAddress((void**)&lpTH,  g_lpTH);
    cudaGetSymbolAddress((void**)&AmH,   g_AmH);
    cudaGetSymbolAddress((void**)&AtH,   g_AtH);
    cudaGetSymbolAddress((void**)&combH, g_combH);
    cudaGetSymbolAddress((void**)&vWTH,  g_vWTH);
    cudaGetSymbolAddress((void**)&lWTH,  g_lWTH);
    cudaGetSymbolAddress((void**)&oWTH,  g_oWTH);
    cudaGetSymbolAddress((void**)&scale, g_scale);

    float* tmp0 = Af;                       // [ROWS,DIM] proj scratch
    float* tmp1 = Af + (size_t)ROWS * DIM;  // [ROWS,DIM]

    const long long SD = (long long)SEQ * DIM;
    const long long SS = (long long)SEQ * SEQ;
    const long long SC = (long long)SEQ * 2 * DIM;
    const int N4 = ROWS * DIM / 4;

    claw_mean_kernel<<<1, 1024>>>(claw);

    // half conversions of raw inputs
    f2h_kernel<<<(N4 + 255) / 256, 256>>>(vis,  visH,  N4);
    f2h_kernel<<<(N4 + 255) / 256, 256>>>(lang, langH, N4);

    // weight transposes (f32 -> half): WT[N,K] = W[K,N]
    transpose_kernel<float, __half><<<dim3(DIM / 32, DIM / 32, 1), dim3(32, 8)>>>(vW, vWTH, DIM, DIM, 0, 0);
    transpose_kernel<float, __half><<<dim3(DIM / 32, DIM / 32, 1), dim3(32, 8)>>>(lW, lWTH, DIM, DIM, 0, 0);
    transpose_kernel<float, __half><<<dim3(DIM / 32, (2 * DIM) / 32, 1), dim3(32, 8)>>>(oW, oWTH, 2 * DIM, DIM, 0, 0);

    // proj GEMMs -> f32 tmp
    h_gemm<float><<<dim3(DIM / 128, ROWS / 128, 1), 256>>>(
        visH, vWTH, tmp0, DIM, DIM, DIM, DIM, 0, 0, 0, nullptr, vb);
    h_gemm<float><<<dim3(DIM / 128, ROWS / 128, 1), 256>>>(
        langH, lWTH, tmp1, DIM, DIM, DIM, DIM, 0, 0, 0, nullptr, lb);

    // LN + ReLU -> half projections
    ln_relu_kernel<__half><<<ROWS, 256>>>(tmp0, vpH, vg, vbeta);
    ln_relu_kernel<__half><<<ROWS, 256>>>(tmp1, lpH, lg, lbeta);

    // transposed projections [S,D] -> [D,S] per batch
    transpose_kernel<__half, __half><<<dim3(DIM / 32, SEQ / 32, BATCH), dim3(32, 8)>>>(vpH, vpTH, SEQ, DIM, SD, SD);
    transpose_kernel<__half, __half><<<dim3(DIM / 32, SEQ / 32, BATCH), dim3(32, 8)>>>(lpH, lpTH, SEQ, DIM, SD, SD);

    // sim = (vp @ lp^T) * scale  -> f32
    h_gemm<float><<<dim3(SEQ / 128, SEQ / 128, BATCH), 256>>>(
        vpH, lpH, Af, DIM, DIM, SEQ, DIM, SD, SD, SS, scale, nullptr);

    // softmax -> half A
    softmax_h_kernel<<<BATCH * SEQ, 256>>>(Af, AmH);

    // A^T
    transpose_kernel<__half, __half><<<dim3(SEQ / 32, SEQ / 32, BATCH), dim3(32, 8)>>>(AmH, AtH, SEQ, SEQ, SS, SS);

    // aligned_vision = A @ vp   -> combH[:, :768]
    h_gemm<__half><<<dim3(DIM / 128, SEQ / 128, BATCH), 256>>>(
        AmH, vpTH, combH, SEQ, SEQ, 2 * DIM, SEQ, SS, SD, SC, nullptr, nullptr);

    // aligned_language = A^T @ lp -> combH[:, 768:]
    h_gemm<__half><<<dim3(DIM / 128, SEQ / 128, BATCH), 256>>>(
        AtH, lpTH, combH + DIM, SEQ, SEQ, 2 * DIM, SEQ, SS, SD, SC, nullptr, nullptr);

    // out_pre = comb @ oW + ob -> f32 (reuse Af)
    h_gemm<float><<<dim3(DIM / 128, ROWS / 128, 1), 256>>>(
        combH, oWTH, Af, 2 * DIM, 2 * DIM, DIM, 2 * DIM, 0, 0, 0, nullptr, ob);

    // final LN + ReLU -> f32 out
    ln_relu_kernel<float><<<ROWS, 256>>>(Af, out, og, obeta);
}

// round 5
// speedup vs baseline: 5.7170x; 1.1542x over previous
#include <cuda_runtime.h>
#include <cuda_fp16.h>
#include <cstdint>

// Static problem shapes
#define BATCH 8
#define SEQ   2048
#define DIM   768
#define ROWS  (BATCH * SEQ)       // 16384
#define TEMP_INV (1.0f / 0.07f)

// ---------------------------------------------------------------------------
// Device-global scratch
// ---------------------------------------------------------------------------
__device__ float  g_tmp[2 * ROWS * DIM];            // f32 proj tmps / out_pre
__device__ __half g_visH [ROWS * DIM];
__device__ __half g_langH[ROWS * DIM];
__device__ __half g_vpH  [ROWS * DIM];
__device__ __half g_lpH  [ROWS * DIM];
__device__ __half g_AmH[(size_t)BATCH * SEQ * SEQ];
__device__ __half g_combH[ROWS * 2 * DIM];
__device__ __half g_vWH[DIM * DIM];
__device__ __half g_lWH[DIM * DIM];
__device__ __half g_oWH[2 * DIM * DIM];
__device__ float  g_scale;

// ---------------------------------------------------------------------------
// PTX helpers
// ---------------------------------------------------------------------------
__device__ __forceinline__ uint32_t smem_u32(const void* p) {
    uint32_t a;
    asm("{ .reg .u64 t; cvta.to.shared.u64 t, %1; cvt.u32.u64 %0, t; }" : "=r"(a) : "l"(p));
    return a;
}
__device__ __forceinline__ void cp16(void* sdst, const void* gsrc) {
    asm volatile("cp.async.cg.shared.global [%0], [%1], 16;"
                 :: "r"(smem_u32(sdst)), "l"(__cvta_generic_to_global(gsrc)) : "memory");
}
__device__ __forceinline__ void ldsm4(uint32_t* r, uint32_t addr) {
    asm volatile("ldmatrix.sync.aligned.m8n8.x4.shared.b16 {%0,%1,%2,%3}, [%4];"
                 : "=r"(r[0]), "=r"(r[1]), "=r"(r[2]), "=r"(r[3]) : "r"(addr));
}
__device__ __forceinline__ void ldsm4t(uint32_t* r, uint32_t addr) {
    asm volatile("ldmatrix.sync.aligned.m8n8.x4.trans.shared.b16 {%0,%1,%2,%3}, [%4];"
                 : "=r"(r[0]), "=r"(r[1]), "=r"(r[2]), "=r"(r[3]) : "r"(addr));
}
__device__ __forceinline__ void mma16816(float* c, const uint32_t* a, const uint32_t* b) {
    asm volatile(
        "mma.sync.aligned.m16n8k16.row.col.f32.f16.f16.f32 "
        "{%0,%1,%2,%3}, {%4,%5,%6,%7}, {%8,%9}, {%0,%1,%2,%3};"
        : "+f"(c[0]), "+f"(c[1]), "+f"(c[2]), "+f"(c[3])
        : "r"(a[0]), "r"(a[1]), "r"(a[2]), "r"(a[3]), "r"(b[0]), "r"(b[1]));
}
__device__ __forceinline__ void store2(float* p, float x, float y) {
    *reinterpret_cast<float2*>(p) = make_float2(x, y);
}
__device__ __forceinline__ void store2(__half* p, float x, float y) {
    *reinterpret_cast<__half2*>(p) = __floats2half2_rn(x, y);
}

// ---------------------------------------------------------------------------
// fp16 mma.sync GEMM: C[M,N] = alpha * opA @ opB + bias
//   TRA=0: A stored [M,K]; TRA=1: A stored [K,M]   (lda = leading stride)
//   TRB=0: B stored [N,K]; TRB=1: B stored [K,N]
// CTA 128x128x32, 8 warps (2x4), warp tile 64x32, ldmatrix(+trans) fragments.
// grid = (N/128, M/128, batch), 256 threads.
// ---------------------------------------------------------------------------
#define SMJ 40    // [128][40] halves layout: conflict-free LDSM
#define SMK 136   // [32][136] halves layout: row step 68 words (=4 mod 32), conflict-free

template <int TRA, int TRB, typename OUT>
__global__ __launch_bounds__(256, 2)
void h_gemm(const __half* __restrict__ Ag, const __half* __restrict__ Bg,
            OUT* __restrict__ Cg,
            int lda, int ldb, int ldc, int K,
            long long sA, long long sB, long long sC,
            const float* __restrict__ alpha_ptr, const float* __restrict__ bias) {
    constexpr int ASZ = TRA ? 32 * SMK : 128 * SMJ;
    constexpr int BSZ = TRB ? 32 * SMK : 128 * SMJ;
    __shared__ __half As[2][ASZ];
    __shared__ __half Bs[2][BSZ];

    const int tid  = threadIdx.x;
    const int wid  = tid >> 5;
    const int lane = tid & 31;
    const int gid  = lane >> 2;
    const int t4   = lane & 3;
    const int warp_m = (wid >> 2) * 64;
    const int warp_n = (wid & 3) * 32;

    const __half* A = Ag + (long long)blockIdx.z * sA
                    + (TRA ? (long long)blockIdx.y * 128 : (long long)blockIdx.y * 128 * lda);
    const __half* B = Bg + (long long)blockIdx.z * sB
                    + (TRB ? (long long)blockIdx.x * 128 : (long long)blockIdx.x * 128 * ldb);

    // ldmatrix lane base offsets (in halves)
    const int aoff = TRA
        ? ((lane & 7) + 8 * (lane >> 4)) * SMK + warp_m + 8 * ((lane >> 3) & 1)
        : (warp_m + (lane & 7) + 8 * ((lane >> 3) & 1)) * SMJ + 8 * (lane >> 4);
    const int boff = TRB
        ? ((lane & 7) + 8 * ((lane >> 3) & 1)) * SMK + warp_n + 8 * (lane >> 4)
        : (warp_n + (lane & 7) + 8 * (lane >> 4)) * SMJ + 8 * ((lane >> 3) & 1);
    uint32_t aBase[2] = { smem_u32(&As[0][aoff]), smem_u32(&As[1][aoff]) };
    uint32_t bBase[2] = { smem_u32(&Bs[0][boff]), smem_u32(&Bs[1][boff]) };

    float acc[4][4][4] = {};
    const int KT = K >> 5;

    auto load_stage = [&](int buf, int kt) {
        const int k0 = kt * 32;
        #pragma unroll
        for (int i = 0; i < 2; i++) {
            int chunk = tid + i * 256;
            if (TRA == 0) {
                int row = chunk >> 2, c = (chunk & 3) * 8;
                cp16(&As[buf][row * SMJ + c], A + (long long)row * lda + k0 + c);
            } else {
                int row = chunk >> 4, c = (chunk & 15) * 8;
                cp16(&As[buf][row * SMK + c], A + (long long)(k0 + row) * lda + c);
            }
            if (TRB == 0) {
                int row = chunk >> 2, c = (chunk & 3) * 8;
                cp16(&Bs[buf][row * SMJ + c], B + (long long)row * ldb + k0 + c);
            } else {
                int row = chunk >> 4, c = (chunk & 15) * 8;
                cp16(&Bs[buf][row * SMK + c], B + (long long)(k0 + row) * ldb + c);
            }
        }
        asm volatile("cp.async.commit_group;" ::: "memory");
    };

    load_stage(0, 0);

    int buf = 0;
    for (int kt = 0; kt < KT; kt++) {
        if (kt + 1 < KT) {
            load_stage(buf ^ 1, kt + 1);
            asm volatile("cp.async.wait_group 1;" ::: "memory");
        } else {
            asm volatile("cp.async.wait_group 0;" ::: "memory");
        }
        __syncthreads();

        #pragma unroll
        for (int ks = 0; ks < 2; ks++) {
            uint32_t afr[4][4], bfr[4][2], btmp[4];
            #pragma unroll
            for (int mb = 0; mb < 4; mb++) {
                if (TRA) ldsm4t(afr[mb], aBase[buf] + (ks * 16 * SMK + mb * 16) * 2);
                else     ldsm4 (afr[mb], aBase[buf] + (mb * 16 * SMJ + ks * 16) * 2);
            }
            #pragma unroll
            for (int h = 0; h < 2; h++) {
                if (TRB) ldsm4t(btmp, bBase[buf] + (ks * 16 * SMK + h * 16) * 2);
                else     ldsm4 (btmp, bBase[buf] + (h * 16 * SMJ + ks * 16) * 2);
                bfr[2 * h][0]     = btmp[0]; bfr[2 * h][1]     = btmp[1];
                bfr[2 * h + 1][0] = btmp[2]; bfr[2 * h + 1][1] = btmp[3];
            }
            #pragma unroll
            for (int mb = 0; mb < 4; mb++)
                #pragma unroll
                for (int nb = 0; nb < 4; nb++)
                    mma16816(acc[mb][nb], afr[mb], bfr[nb]);
        }
        __syncthreads();
        buf ^= 1;
    }

    const float alpha = alpha_ptr ? *alpha_ptr : 1.0f;
    OUT* C = Cg + (long long)blockIdx.z * sC + (long long)blockIdx.y * 128 * ldc
           + (long long)blockIdx.x * 128;
    const int colbase = blockIdx.x * 128;
    #pragma unroll
    for (int mb = 0; mb < 4; mb++) {
        const int row = warp_m + mb * 16 + gid;
        #pragma unroll
        for (int nb = 0; nb < 4; nb++) {
            const int col = warp_n + nb * 8 + 2 * t4;
            float bx = 0.0f, by = 0.0f;
            if (bias) { bx = bias[colbase + col]; by = bias[colbase + col + 1]; }
            store2(&C[(long long)row * ldc + col],
                   acc[mb][nb][0] * alpha + bx, acc[mb][nb][1] * alpha + by);
            store2(&C[(long long)(row + 8) * ldc + col],
                   acc[mb][nb][2] * alpha + bx, acc[mb][nb][3] * alpha + by);
        }
    }
}

// ---------------------------------------------------------------------------
// float -> half bulk convert
// ---------------------------------------------------------------------------
__global__ void f2h_kernel(const float* __restrict__ in, __half* __restrict__ out, int n4) {
    int i = blockIdx.x * blockDim.x + threadIdx.x;
    if (i < n4) {
        float4 v = reinterpret_cast<const float4*>(in)[i];
        __half2* o = reinterpret_cast<__half2*>(out);
        o[2 * i]     = __floats2half2_rn(v.x, v.y);
        o[2 * i + 1] = __floats2half2_rn(v.z, v.w);
    }
}

// ---------------------------------------------------------------------------
// claw mean -> g_scale
// ---------------------------------------------------------------------------
__global__ void claw_mean_kernel(const float* __restrict__ claw) {
    __shared__ float red[1024];
    int tid = threadIdx.x;
    float s = 0.0f;
    for (int i = tid; i < DIM * DIM; i += 1024) s += claw[i];
    red[tid] = s;
    __syncthreads();
    for (int o = 512; o > 0; o >>= 1) {
        if (tid < o) red[tid] += red[tid + o];
        __syncthreads();
    }
    if (tid == 0) g_scale = (red[0] / (float)(DIM * DIM)) * TEMP_INV;
}

// ---------------------------------------------------------------------------
// LayerNorm (+ReLU), last dim 768. One block (256) per row. f32 in, OUT out.
// ---------------------------------------------------------------------------
template <typename OUT>
__global__ void ln_relu_kernel(const float* __restrict__ X, OUT* __restrict__ Y,
                               const float* __restrict__ g, const float* __restrict__ beta) {
    __shared__ float red[256];
    const int tid = threadIdx.x;
    const float* x = X + (long long)blockIdx.x * DIM;
    OUT*         y = Y + (long long)blockIdx.x * DIM;

    float v0 = x[tid], v1 = x[tid + 256], v2 = x[tid + 512];
    red[tid] = v0 + v1 + v2;
    __syncthreads();
    for (int o = 128; o > 0; o >>= 1) { if (tid < o) red[tid] += red[tid + o]; __syncthreads(); }
    const float m = red[0] * (1.0f / DIM);
    __syncthreads();
    float d0 = v0 - m, d1 = v1 - m, d2 = v2 - m;
    red[tid] = d0 * d0 + d1 * d1 + d2 * d2;
    __syncthreads();
    for (int o = 128; o > 0; o >>= 1) { if (tid < o) red[tid] += red[tid + o]; __syncthreads(); }
    const float rs = rsqrtf(red[0] * (1.0f / DIM) + 1e-5f);
    y[tid]       = (OUT)fmaxf(0.0f, d0 * rs * g[tid]       + beta[tid]);
    y[tid + 256] = (OUT)fmaxf(0.0f, d1 * rs * g[tid + 256] + beta[tid + 256]);
    y[tid + 512] = (OUT)fmaxf(0.0f, d2 * rs * g[tid + 512] + beta[tid + 512]);
}

// ---------------------------------------------------------------------------
// Row softmax over 2048, half, in place. One block (256) per row.
// ---------------------------------------------------------------------------
__global__ void softmax_h_kernel(__half* __restrict__ X) {
    __shared__ float red[256];
    const int tid = threadIdx.x;
    __half2* x = reinterpret_cast<__half2*>(X + (long long)blockIdx.x * SEQ);

    float2 v[4];
    #pragma unroll
    for (int i = 0; i < 4; i++) v[i] = __half22float2(x[tid * 4 + i]);

    float mx = v[0].x;
    #pragma unroll
    for (int i = 0; i < 4; i++) mx = fmaxf(mx, fmaxf(v[i].x, v[i].y));
    red[tid] = mx;
    __syncthreads();
    for (int s = 128; s > 0; s >>= 1) { if (tid < s) red[tid] = fmaxf(red[tid], red[tid + s]); __syncthreads(); }
    mx = red[0];
    __syncthreads();

    float sum = 0.0f;
    #pragma unroll
    for (int i = 0; i < 4; i++) {
        v[i].x = expf(v[i].x - mx); v[i].y = expf(v[i].y - mx);
        sum += v[i].x + v[i].y;
    }
    red[tid] = sum;
    __syncthreads();
    for (int s = 128; s > 0; s >>= 1) { if (tid < s) red[tid] += red[tid + s]; __syncthreads(); }
    const float inv = 1.0f / red[0];
    #pragma unroll
    for (int i = 0; i < 4; i++)
        x[tid * 4 + i] = __floats2half2_rn(v[i].x * inv, v[i].y * inv);
}

// ---------------------------------------------------------------------------
// Launch
// ---------------------------------------------------------------------------
extern "C" void kernel_launch(void* const* d_in, const int* in_sizes, int n_in,
                              void* d_out, int out_size) {
    const float* vis   = (const float*)d_in[0];
    const float* lang  = (const float*)d_in[1];
    const float* vW    = (const float*)d_in[2];
    const float* vb    = (const float*)d_in[3];
    const float* vg    = (const float*)d_in[4];
    const float* vbeta = (const float*)d_in[5];
    const float* lW    = (const float*)d_in[6];
    const float* lb    = (const float*)d_in[7];
    const float* lg    = (const float*)d_in[8];
    const float* lbeta = (const float*)d_in[9];
    const float* claw  = (const float*)d_in[10];
    const float* oW    = (const float*)d_in[11];
    const float* ob    = (const float*)d_in[12];
    const float* og    = (const float*)d_in[13];
    const float* obeta = (const float*)d_in[14];
    float* out = (float*)d_out;

    float  *tmp, *scale;
    __half *visH, *langH, *vpH, *lpH, *AmH, *combH, *vWH, *lWH, *oWH;
    cudaGetSymbolAddress((void**)&tmp,   g_tmp);
    cudaGetSymbolAddress((void**)&visH,  g_visH);
    cudaGetSymbolAddress((void**)&langH, g_langH);
    cudaGetSymbolAddress((void**)&vpH,   g_vpH);
    cudaGetSymbolAddress((void**)&lpH,   g_lpH);
    cudaGetSymbolAddress((void**)&AmH,   g_AmH);
    cudaGetSymbolAddress((void**)&combH, g_combH);
    cudaGetSymbolAddress((void**)&vWH,   g_vWH);
    cudaGetSymbolAddress((void**)&lWH,   g_lWH);
    cudaGetSymbolAddress((void**)&oWH,   g_oWH);
    cudaGetSymbolAddress((void**)&scale, g_scale);

    float* tmp0 = tmp;
    float* tmp1 = tmp + (size_t)ROWS * DIM;

    const long long SD = (long long)SEQ * DIM;
    const long long SS = (long long)SEQ * SEQ;
    const long long SC = (long long)SEQ * 2 * DIM;
    const int N4  = ROWS * DIM / 4;
    const int W4  = DIM * DIM / 4;
    const int OW4 = 2 * DIM * DIM / 4;

    claw_mean_kernel<<<1, 1024>>>(claw);

    f2h_kernel<<<(N4 + 255) / 256, 256>>>(vis,  visH,  N4);
    f2h_kernel<<<(N4 + 255) / 256, 256>>>(lang, langH, N4);
    f2h_kernel<<<(W4 + 255) / 256, 256>>>(vW, vWH, W4);
    f2h_kernel<<<(W4 + 255) / 256, 256>>>(lW, lWH, W4);
    f2h_kernel<<<(OW4 + 255) / 256, 256>>>(oW, oWH, OW4);

    h_gemm<0, 1, float><<<dim3(DIM / 128, ROWS / 128, 1), 256>>>(
        visH, vWH, tmp0, DIM, DIM, DIM, DIM, 0, 0, 0, nullptr, vb);
    h_gemm<0, 1, float><<<dim3(DIM / 128, ROWS / 128, 1), 256>>>(
        langH, lWH, tmp1, DIM, DIM, DIM, DIM, 0, 0, 0, nullptr, lb);

    ln_relu_kernel<__half><<<ROWS, 256>>>(tmp0, vpH, vg, vbeta);
    ln_relu_kernel<__half><<<ROWS, 256>>>(tmp1, lpH, lg, lbeta);

    // sim = (vp @ lp^T) * scale -> half
    h_gemm<0, 0, __half><<<dim3(SEQ / 128, SEQ / 128, BATCH), 256>>>(
        vpH, lpH, AmH, DIM, DIM, SEQ, DIM, SD, SD, SS, scale, nullptr);

    softmax_h_kernel<<<BATCH * SEQ, 256>>>(AmH);

    // aligned_vision = A @ vp
    h_gemm<0, 1, __half><<<dim3(DIM / 128, SEQ / 128, BATCH), 256>>>(
        AmH, vpH, combH, SEQ, DIM, 2 * DIM, SEQ, SS, SD, SC, nullptr, nullptr);

    // aligned_language = A^T @ lp
    h_gemm<1, 1, __half><<<dim3(DIM / 128, SEQ / 128, BATCH), 256>>>(
        AmH, lpH, combH + DIM, SEQ, DIM, 2 * DIM, SEQ, SS, SD, SC, nullptr, nullptr);

    // out_pre = comb @ oW + ob
    h_gemm<0, 1, float><<<dim3(DIM / 128, ROWS / 128, 1), 256>>>(
        combH, oWH, tmp0, 2 * DIM, DIM, DIM, 2 * DIM, 0, 0, 0, nullptr, ob);

    ln_relu_kernel<float><<<ROWS, 256>>>(tmp0, out, og, obeta);
}

// round 6
// speedup vs baseline: 6.1240x; 1.0712x over previous
#include <cuda_runtime.h>
#include <cuda_fp16.h>
#include <cstdint>

// Static problem shapes
#define BATCH 8
#define SEQ   2048
#define DIM   768
#define ROWS  (BATCH * SEQ)       // 16384
#define TEMP_INV (1.0f / 0.07f)

// ---------------------------------------------------------------------------
// Device-global scratch
// ---------------------------------------------------------------------------
__device__ float  g_tmp[2 * ROWS * DIM];            // f32 proj tmps / out_pre
__device__ __half g_visH [ROWS * DIM];
__device__ __half g_langH[ROWS * DIM];
__device__ __half g_vpH  [ROWS * DIM];
__device__ __half g_lpH  [ROWS * DIM];
__device__ __half g_AmH[(size_t)BATCH * SEQ * SEQ];
__device__ __half g_combH[ROWS * 2 * DIM];
__device__ __half g_vWH[DIM * DIM];
__device__ __half g_lWH[DIM * DIM];
__device__ __half g_oWH[2 * DIM * DIM];
__device__ float  g_scale;

// ---------------------------------------------------------------------------
// PTX helpers
// ---------------------------------------------------------------------------
__device__ __forceinline__ uint32_t smem_u32(const void* p) {
    uint32_t a;
    asm("{ .reg .u64 t; cvta.to.shared.u64 t, %1; cvt.u32.u64 %0, t; }" : "=r"(a) : "l"(p));
    return a;
}
__device__ __forceinline__ void cp16(void* sdst, const void* gsrc) {
    asm volatile("cp.async.cg.shared.global [%0], [%1], 16;"
                 :: "r"(smem_u32(sdst)), "l"(__cvta_generic_to_global(gsrc)) : "memory");
}
__device__ __forceinline__ void ldsm4(uint32_t* r, uint32_t addr) {
    asm volatile("ldmatrix.sync.aligned.m8n8.x4.shared.b16 {%0,%1,%2,%3}, [%4];"
                 : "=r"(r[0]), "=r"(r[1]), "=r"(r[2]), "=r"(r[3]) : "r"(addr));
}
__device__ __forceinline__ void ldsm4t(uint32_t* r, uint32_t addr) {
    asm volatile("ldmatrix.sync.aligned.m8n8.x4.trans.shared.b16 {%0,%1,%2,%3}, [%4];"
                 : "=r"(r[0]), "=r"(r[1]), "=r"(r[2]), "=r"(r[3]) : "r"(addr));
}
__device__ __forceinline__ void mma16816(float* c, const uint32_t* a, const uint32_t* b) {
    asm volatile(
        "mma.sync.aligned.m16n8k16.row.col.f32.f16.f16.f32 "
        "{%0,%1,%2,%3}, {%4,%5,%6,%7}, {%8,%9}, {%0,%1,%2,%3};"
        : "+f"(c[0]), "+f"(c[1]), "+f"(c[2]), "+f"(c[3])
        : "r"(a[0]), "r"(a[1]), "r"(a[2]), "r"(a[3]), "r"(b[0]), "r"(b[1]));
}
__device__ __forceinline__ void store2(float* p, float x, float y) {
    *reinterpret_cast<float2*>(p) = make_float2(x, y);
}
__device__ __forceinline__ void store2(__half* p, float x, float y) {
    *reinterpret_cast<__half2*>(p) = __floats2half2_rn(x, y);
}

// ---------------------------------------------------------------------------
// fp16 mma.sync GEMM: C[M,N] = alpha * opA @ opB + bias
//   TRA=0: A stored [M,K]; TRA=1: A stored [K,M]   (lda = leading stride)
//   TRB=0: B stored [N,K]; TRB=1: B stored [K,N]
// CTA 128x128x32, 8 warps (2x4), warp tile 64x32, ldmatrix(+trans).
// 3-stage cp.async pipeline, one __syncthreads per k-iteration.
// grid = (N/128, M/128, batch), 256 threads, dynamic smem.
// ---------------------------------------------------------------------------
#define SMJ 40    // [128][40] halves: conflict-free LDSM
#define SMK 136   // [32][136] halves: row step 68 words (=4 mod 32), conflict-free

template <int TRA, int TRB>
struct GemmSmem {
    static constexpr int AH = TRA ? 32 * SMK : 128 * SMJ;  // halves per A stage
    static constexpr int BH = TRB ? 32 * SMK : 128 * SMJ;
    static constexpr int BYTES = 3 * (AH + BH) * 2;
};

template <int TRA, int TRB, typename OUT>
__global__ __launch_bounds__(256, 2)
void h_gemm(const __half* __restrict__ Ag, const __half* __restrict__ Bg,
            OUT* __restrict__ Cg,
            int lda, int ldb, int ldc, int K,
            long long sA, long long sB, long long sC,
            const float* __restrict__ alpha_ptr, const float* __restrict__ bias) {
    constexpr int AH = GemmSmem<TRA, TRB>::AH;
    constexpr int BH = GemmSmem<TRA, TRB>::BH;
    extern __shared__ char dynsm[];
    __half* Asm = reinterpret_cast<__half*>(dynsm);
    __half* Bsm = Asm + 3 * AH;

    const int tid  = threadIdx.x;
    const int wid  = tid >> 5;
    const int lane = tid & 31;
    const int gid  = lane >> 2;
    const int t4   = lane & 3;
    const int warp_m = (wid >> 2) * 64;
    const int warp_n = (wid & 3) * 32;

    const __half* A = Ag + (long long)blockIdx.z * sA
                    + (TRA ? (long long)blockIdx.y * 128 : (long long)blockIdx.y * 128 * lda);
    const __half* B = Bg + (long long)blockIdx.z * sB
                    + (TRB ? (long long)blockIdx.x * 128 : (long long)blockIdx.x * 128 * ldb);

    // ldmatrix lane base offsets (halves, within a stage)
    const int aoff = TRA
        ? ((lane & 7) + 8 * (lane >> 4)) * SMK + warp_m + 8 * ((lane >> 3) & 1)
        : (warp_m + (lane & 7) + 8 * ((lane >> 3) & 1)) * SMJ + 8 * (lane >> 4);
    const int boff = TRB
        ? ((lane & 7) + 8 * ((lane >> 3) & 1)) * SMK + warp_n + 8 * (lane >> 4)
        : (warp_n + (lane & 7) + 8 * (lane >> 4)) * SMJ + 8 * ((lane >> 3) & 1);
    const uint32_t aBase0 = smem_u32(&Asm[aoff]);
    const uint32_t bBase0 = smem_u32(&Bsm[boff]);

    float acc[4][4][4] = {};
    const int KT = K >> 5;

    auto load_stage = [&](int st, int kt) {
        const int k0 = kt * 32;
        __half* As = Asm + st * AH;
        __half* Bs = Bsm + st * BH;
        #pragma unroll
        for (int i = 0; i < 2; i++) {
            int chunk = tid + i * 256;
            if (TRA == 0) {
                int row = chunk >> 2, c = (chunk & 3) * 8;
                cp16(&As[row * SMJ + c], A + (long long)row * lda + k0 + c);
            } else {
                int row = chunk >> 4, c = (chunk & 15) * 8;
                cp16(&As[row * SMK + c], A + (long long)(k0 + row) * lda + c);
            }
            if (TRB == 0) {
                int row = chunk >> 2, c = (chunk & 3) * 8;
                cp16(&Bs[row * SMJ + c], B + (long long)row * ldb + k0 + c);
            } else {
                int row = chunk >> 4, c = (chunk & 15) * 8;
                cp16(&Bs[row * SMK + c], B + (long long)(k0 + row) * ldb + c);
            }
        }
        asm volatile("cp.async.commit_group;" ::: "memory");
    };

    // prologue: stages 0,1
    load_stage(0, 0);
    if (KT > 1) load_stage(1, 1);

    int sc = 0, sl = 2;
    for (int kt = 0; kt < KT; kt++) {
        if (kt + 1 < KT) asm volatile("cp.async.wait_group 1;" ::: "memory");
        else             asm volatile("cp.async.wait_group 0;" ::: "memory");
        __syncthreads();

        if (kt + 2 < KT) load_stage(sl, kt + 2);

        const uint32_t aB = aBase0 + sc * AH * 2;
        const uint32_t bB = bBase0 + sc * BH * 2;
        #pragma unroll
        for (int ks = 0; ks < 2; ks++) {
            uint32_t afr[4][4], bfr[4][2], btmp[4];
            #pragma unroll
            for (int mb = 0; mb < 4; mb++) {
                if (TRA) ldsm4t(afr[mb], aB + (ks * 16 * SMK + mb * 16) * 2);
                else     ldsm4 (afr[mb], aB + (mb * 16 * SMJ + ks * 16) * 2);
            }
            #pragma unroll
            for (int h = 0; h < 2; h++) {
                if (TRB) ldsm4t(btmp, bB + (ks * 16 * SMK + h * 16) * 2);
                else     ldsm4 (btmp, bB + (h * 16 * SMJ + ks * 16) * 2);
                bfr[2 * h][0]     = btmp[0]; bfr[2 * h][1]     = btmp[1];
                bfr[2 * h + 1][0] = btmp[2]; bfr[2 * h + 1][1] = btmp[3];
            }
            #pragma unroll
            for (int mb = 0; mb < 4; mb++)
                #pragma unroll
                for (int nb = 0; nb < 4; nb++)
                    mma16816(acc[mb][nb], afr[mb], bfr[nb]);
        }
        sc = (sc == 2) ? 0 : sc + 1;
        sl = (sl == 2) ? 0 : sl + 1;
    }

    const float alpha = alpha_ptr ? *alpha_ptr : 1.0f;
    OUT* C = Cg + (long long)blockIdx.z * sC + (long long)blockIdx.y * 128 * ldc
           + (long long)blockIdx.x * 128;
    const int colbase = blockIdx.x * 128;
    #pragma unroll
    for (int mb = 0; mb < 4; mb++) {
        const int row = warp_m + mb * 16 + gid;
        #pragma unroll
        for (int nb = 0; nb < 4; nb++) {
            const int col = warp_n + nb * 8 + 2 * t4;
            float bx = 0.0f, by = 0.0f;
            if (bias) { bx = bias[colbase + col]; by = bias[colbase + col + 1]; }
            store2(&C[(long long)row * ldc + col],
                   acc[mb][nb][0] * alpha + bx, acc[mb][nb][1] * alpha + by);
            store2(&C[(long long)(row + 8) * ldc + col],
                   acc[mb][nb][2] * alpha + bx, acc[mb][nb][3] * alpha + by);
        }
    }
}

// ---------------------------------------------------------------------------
// float -> half bulk convert
// ---------------------------------------------------------------------------
__global__ void f2h_kernel(const float* __restrict__ in, __half* __restrict__ out, int n4) {
    int i = blockIdx.x * blockDim.x + threadIdx.x;
    if (i < n4) {
        float4 v = reinterpret_cast<const float4*>(in)[i];
        __half2* o = reinterpret_cast<__half2*>(out);
        o[2 * i]     = __floats2half2_rn(v.x, v.y);
        o[2 * i + 1] = __floats2half2_rn(v.z, v.w);
    }
}

// ---------------------------------------------------------------------------
// claw mean -> g_scale
// ---------------------------------------------------------------------------
__global__ void claw_mean_kernel(const float* __restrict__ claw) {
    __shared__ float red[1024];
    int tid = threadIdx.x;
    float s = 0.0f;
    for (int i = tid; i < DIM * DIM; i += 1024) s += claw[i];
    red[tid] = s;
    __syncthreads();
    for (int o = 512; o > 0; o >>= 1) {
        if (tid < o) red[tid] += red[tid + o];
        __syncthreads();
    }
    if (tid == 0) g_scale = (red[0] / (float)(DIM * DIM)) * TEMP_INV;
}

// ---------------------------------------------------------------------------
// Block reduction helpers (256 threads): shuffle + 8-entry smem broadcast
// ---------------------------------------------------------------------------
__device__ __forceinline__ float blk_sum256(float v, float* ws, int tid) {
    #pragma unroll
    for (int o = 16; o > 0; o >>= 1) v += __shfl_xor_sync(0xFFFFFFFFu, v, o);
    if ((tid & 31) == 0) ws[tid >> 5] = v;
    __syncthreads();
    float t = ws[0];
    #pragma unroll
    for (int i = 1; i < 8; i++) t += ws[i];
    return t;
}
__device__ __forceinline__ float blk_max256(float v, float* ws, int tid) {
    #pragma unroll
    for (int o = 16; o > 0; o >>= 1) v = fmaxf(v, __shfl_xor_sync(0xFFFFFFFFu, v, o));
    if ((tid & 31) == 0) ws[tid >> 5] = v;
    __syncthreads();
    float t = ws[0];
    #pragma unroll
    for (int i = 1; i < 8; i++) t = fmaxf(t, ws[i]);
    return t;
}

// ---------------------------------------------------------------------------
// LayerNorm (+ReLU), last dim 768. One block (256) per row. f32 in, OUT out.
// ---------------------------------------------------------------------------
template <typename OUT>
__global__ void ln_relu_kernel(const float* __restrict__ X, OUT* __restrict__ Y,
                               const float* __restrict__ g, const float* __restrict__ beta) {
    __shared__ float ws1[8], ws2[8];
    const int tid = threadIdx.x;
    const float* x = X + (long long)blockIdx.x * DIM;
    OUT*         y = Y + (long long)blockIdx.x * DIM;

    float v0 = x[tid], v1 = x[tid + 256], v2 = x[tid + 512];
    const float m = blk_sum256(v0 + v1 + v2, ws1, tid) * (1.0f / DIM);
    float d0 = v0 - m, d1 = v1 - m, d2 = v2 - m;
    const float var = blk_sum256(d0 * d0 + d1 * d1 + d2 * d2, ws2, tid) * (1.0f / DIM);
    const float rs = rsqrtf(var + 1e-5f);
    y[tid]       = (OUT)fmaxf(0.0f, d0 * rs * g[tid]       + beta[tid]);
    y[tid + 256] = (OUT)fmaxf(0.0f, d1 * rs * g[tid + 256] + beta[tid + 256]);
    y[tid + 512] = (OUT)fmaxf(0.0f, d2 * rs * g[tid + 512] + beta[tid + 512]);
}

// ---------------------------------------------------------------------------
// Row softmax over 2048, half, in place. One block (256) per row.
// ---------------------------------------------------------------------------
__global__ void softmax_h_kernel(__half* __restrict__ X) {
    __shared__ float ws1[8], ws2[8];
    const int tid = threadIdx.x;
    __half2* x = reinterpret_cast<__half2*>(X + (long long)blockIdx.x * SEQ);

    float2 v[4];
    #pragma unroll
    for (int i = 0; i < 4; i++) v[i] = __half22float2(x[tid * 4 + i]);

    float mx = v[0].x;
    #pragma unroll
    for (int i = 0; i < 4; i++) mx = fmaxf(mx, fmaxf(v[i].x, v[i].y));
    mx = blk_max256(mx, ws1, tid);

    float sum = 0.0f;
    #pragma unroll
    for (int i = 0; i < 4; i++) {
        v[i].x = expf(v[i].x - mx); v[i].y = expf(v[i].y - mx);
        sum += v[i].x + v[i].y;
    }
    sum = blk_sum256(sum, ws2, tid);
    const float inv = 1.0f / sum;
    #pragma unroll
    for (int i = 0; i < 4; i++)
        x[tid * 4 + i] = __floats2half2_rn(v[i].x * inv, v[i].y * inv);
}

// ---------------------------------------------------------------------------
// Launch
// ---------------------------------------------------------------------------
extern "C" void kernel_launch(void* const* d_in, const int* in_sizes, int n_in,
                              void* d_out, int out_size) {
    const float* vis   = (const float*)d_in[0];
    const float* lang  = (const float*)d_in[1];
    const float* vW    = (const float*)d_in[2];
    const float* vb    = (const float*)d_in[3];
    const float* vg    = (const float*)d_in[4];
    const float* vbeta = (const float*)d_in[5];
    const float* lW    = (const float*)d_in[6];
    const float* lb    = (const float*)d_in[7];
    const float* lg    = (const float*)d_in[8];
    const float* lbeta = (const float*)d_in[9];
    const float* claw  = (const float*)d_in[10];
    const float* oW    = (const float*)d_in[11];
    const float* ob    = (const float*)d_in[12];
    const float* og    = (const float*)d_in[13];
    const float* obeta = (const float*)d_in[14];
    float* out = (float*)d_out;

    float  *tmp, *scale;
    __half *visH, *langH, *vpH, *lpH, *AmH, *combH, *vWH, *lWH, *oWH;
    cudaGetSymbolAddress((void**)&tmp,   g_tmp);
    cudaGetSymbolAddress((void**)&visH,  g_visH);
    cudaGetSymbolAddress((void**)&langH, g_langH);
    cudaGetSymbolAddress((void**)&vpH,   g_vpH);
    cudaGetSymbolAddress((void**)&lpH,   g_lpH);
    cudaGetSymbolAddress((void**)&AmH,   g_AmH);
    cudaGetSymbolAddress((void**)&combH, g_combH);
    cudaGetSymbolAddress((void**)&vWH,   g_vWH);
    cudaGetSymbolAddress((void**)&lWH,   g_lWH);
    cudaGetSymbolAddress((void**)&oWH,   g_oWH);
    cudaGetSymbolAddress((void**)&scale, g_scale);

    float* tmp0 = tmp;
    float* tmp1 = tmp + (size_t)ROWS * DIM;

    const long long SD = (long long)SEQ * DIM;
    const long long SS = (long long)SEQ * SEQ;
    const long long SC = (long long)SEQ * 2 * DIM;
    const int N4  = ROWS * DIM / 4;
    const int W4  = DIM * DIM / 4;
    const int OW4 = 2 * DIM * DIM / 4;

    constexpr int SM01 = GemmSmem<0, 1>::BYTES;   // 61440
    constexpr int SM00 = GemmSmem<0, 0>::BYTES;   // 61440
    constexpr int SM11 = GemmSmem<1, 1>::BYTES;   // 56832
    cudaFuncSetAttribute(h_gemm<0, 1, float>,  cudaFuncAttributeMaxDynamicSharedMemorySize, SM01);
    cudaFuncSetAttribute(h_gemm<0, 0, __half>, cudaFuncAttributeMaxDynamicSharedMemorySize, SM00);
    cudaFuncSetAttribute(h_gemm<0, 1, __half>, cudaFuncAttributeMaxDynamicSharedMemorySize, SM01);
    cudaFuncSetAttribute(h_gemm<1, 1, __half>, cudaFuncAttributeMaxDynamicSharedMemorySize, SM11);

    claw_mean_kernel<<<1, 1024>>>(claw);

    f2h_kernel<<<(N4 + 255) / 256, 256>>>(vis,  visH,  N4);
    f2h_kernel<<<(N4 + 255) / 256, 256>>>(lang, langH, N4);
    f2h_kernel<<<(W4 + 255) / 256, 256>>>(vW, vWH, W4);
    f2h_kernel<<<(W4 + 255) / 256, 256>>>(lW, lWH, W4);
    f2h_kernel<<<(OW4 + 255) / 256, 256>>>(oW, oWH, OW4);

    h_gemm<0, 1, float><<<dim3(DIM / 128, ROWS / 128, 1), 256, SM01>>>(
        visH, vWH, tmp0, DIM, DIM, DIM, DIM, 0, 0, 0, nullptr, vb);
    h_gemm<0, 1, float><<<dim3(DIM / 128, ROWS / 128, 1), 256, SM01>>>(
        langH, lWH, tmp1, DIM, DIM, DIM, DIM, 0, 0, 0, nullptr, lb);

    ln_relu_kernel<__half><<<ROWS, 256>>>(tmp0, vpH, vg, vbeta);
    ln_relu_kernel<__half><<<ROWS, 256>>>(tmp1, lpH, lg, lbeta);

    // sim = (vp @ lp^T) * scale -> half
    h_gemm<0, 0, __half><<<dim3(SEQ / 128, SEQ / 128, BATCH), 256, SM00>>>(
        vpH, lpH, AmH, DIM, DIM, SEQ, DIM, SD, SD, SS, scale, nullptr);

    softmax_h_kernel<<<BATCH * SEQ, 256>>>(AmH);

    // aligned_vision = A @ vp
    h_gemm<0, 1, __half><<<dim3(DIM / 128, SEQ / 128, BATCH), 256, SM01>>>(
        AmH, vpH, combH, SEQ, DIM, 2 * DIM, SEQ, SS, SD, SC, nullptr, nullptr);

    // aligned_language = A^T @ lp
    h_gemm<1, 1, __half><<<dim3(DIM / 128, SEQ / 128, BATCH), 256, SM11>>>(
        AmH, lpH, combH + DIM, SEQ, DIM, 2 * DIM, SEQ, SS, SD, SC, nullptr, nullptr);

    // out_pre = comb @ oW + ob
    h_gemm<0, 1, float><<<dim3(DIM / 128, ROWS / 128, 1), 256, SM01>>>(
        combH, oWH, tmp0, 2 * DIM, DIM, DIM, 2 * DIM, 0, 0, 0, nullptr, ob);

    ln_relu_kernel<float><<<ROWS, 256>>>(tmp0, out, og, obeta);
}

// round 7
// speedup vs baseline: 6.6375x; 1.0839x over previous
#include <cuda_runtime.h>
#include <cuda_fp16.h>
#include <cstdint>

// Static problem shapes
#define BATCH 8
#define SEQ   2048
#define DIM   768
#define ROWS  (BATCH * SEQ)       // 16384
#define TEMP_INV (1.0f / 0.07f)

// ---------------------------------------------------------------------------
// Device-global scratch (all-half intermediates)
// ---------------------------------------------------------------------------
__device__ __half g_visH [ROWS * DIM];
__device__ __half g_langH[ROWS * DIM];
__device__ __half g_vpH  [ROWS * DIM];
__device__ __half g_lpH  [ROWS * DIM];
__device__ __half g_AmH[(size_t)BATCH * SEQ * SEQ];
__device__ __half g_combH[ROWS * 2 * DIM];         // also reused as proj-GEMM tmp
__device__ __half g_vWH[DIM * DIM];
__device__ __half g_lWH[DIM * DIM];
__device__ __half g_oWH[2 * DIM * DIM];
__device__ float  g_part[144];
__device__ float  g_scale;

// ---------------------------------------------------------------------------
// PTX helpers
// ---------------------------------------------------------------------------
__device__ __forceinline__ uint32_t smem_u32(const void* p) {
    uint32_t a;
    asm("{ .reg .u64 t; cvta.to.shared.u64 t, %1; cvt.u32.u64 %0, t; }" : "=r"(a) : "l"(p));
    return a;
}
__device__ __forceinline__ void cp16(void* sdst, const void* gsrc) {
    asm volatile("cp.async.cg.shared.global [%0], [%1], 16;"
                 :: "r"(smem_u32(sdst)), "l"(__cvta_generic_to_global(gsrc)) : "memory");
}
__device__ __forceinline__ void ldsm4(uint32_t* r, uint32_t addr) {
    asm volatile("ldmatrix.sync.aligned.m8n8.x4.shared.b16 {%0,%1,%2,%3}, [%4];"
                 : "=r"(r[0]), "=r"(r[1]), "=r"(r[2]), "=r"(r[3]) : "r"(addr));
}
__device__ __forceinline__ void ldsm4t(uint32_t* r, uint32_t addr) {
    asm volatile("ldmatrix.sync.aligned.m8n8.x4.trans.shared.b16 {%0,%1,%2,%3}, [%4];"
                 : "=r"(r[0]), "=r"(r[1]), "=r"(r[2]), "=r"(r[3]) : "r"(addr));
}
__device__ __forceinline__ void mma16816(float* c, const uint32_t* a, const uint32_t* b) {
    asm volatile(
        "mma.sync.aligned.m16n8k16.row.col.f32.f16.f16.f32 "
        "{%0,%1,%2,%3}, {%4,%5,%6,%7}, {%8,%9}, {%0,%1,%2,%3};"
        : "+f"(c[0]), "+f"(c[1]), "+f"(c[2]), "+f"(c[3])
        : "r"(a[0]), "r"(a[1]), "r"(a[2]), "r"(a[3]), "r"(b[0]), "r"(b[1]));
}
__device__ __forceinline__ void store2(float* p, float x, float y) {
    *reinterpret_cast<float2*>(p) = make_float2(x, y);
}
__device__ __forceinline__ void store2(__half* p, float x, float y) {
    *reinterpret_cast<__half2*>(p) = __floats2half2_rn(x, y);
}

// ---------------------------------------------------------------------------
// fp16 mma.sync GEMM: C[M,N] = alpha * opA @ opB + bias
//   TRA=0: A stored [M,K]; TRA=1: A stored [K,M]   (lda = leading stride)
//   TRB=0: B stored [N,K]; TRB=1: B stored [K,N]
// CTA 128x128x64, 8 warps (2x4), warp tile 64x32, ldmatrix(+trans).
// 3-stage cp.async pipeline, one __syncthreads per 64-k iteration.
// grid = (N/128, M/128, batch), 256 threads, dynamic smem (~105KB, 2 CTA/SM).
// ---------------------------------------------------------------------------
#define SMJ 72    // [128][72] halves: row step 36 words (=4 mod 32), LDSM conflict-free
#define SMK 136   // [64][136] halves: row step 68 words (=4 mod 32), conflict-free

template <int TRA, int TRB>
struct GemmSmem {
    static constexpr int AH = TRA ? 64 * SMK : 128 * SMJ;  // halves per A stage
    static constexpr int BH = TRB ? 64 * SMK : 128 * SMJ;
    static constexpr int BYTES = 3 * (AH + BH) * 2;
};

template <int TRA, int TRB, typename OUT>
__global__ __launch_bounds__(256, 2)
void h_gemm(const __half* __restrict__ Ag, const __half* __restrict__ Bg,
            OUT* __restrict__ Cg,
            int lda, int ldb, int ldc, int K,
            long long sA, long long sB, long long sC,
            const float* __restrict__ alpha_ptr, const float* __restrict__ bias) {
    constexpr int AH = GemmSmem<TRA, TRB>::AH;
    constexpr int BH = GemmSmem<TRA, TRB>::BH;
    extern __shared__ char dynsm[];
    __half* Asm = reinterpret_cast<__half*>(dynsm);
    __half* Bsm = Asm + 3 * AH;

    const int tid  = threadIdx.x;
    const int wid  = tid >> 5;
    const int lane = tid & 31;
    const int gid  = lane >> 2;
    const int t4   = lane & 3;
    const int warp_m = (wid >> 2) * 64;
    const int warp_n = (wid & 3) * 32;

    const __half* A = Ag + (long long)blockIdx.z * sA
                    + (TRA ? (long long)blockIdx.y * 128 : (long long)blockIdx.y * 128 * lda);
    const __half* B = Bg + (long long)blockIdx.z * sB
                    + (TRB ? (long long)blockIdx.x * 128 : (long long)blockIdx.x * 128 * ldb);

    // ldmatrix lane base offsets (halves, within a stage)
    const int aoff = TRA
        ? ((lane & 7) + 8 * (lane >> 4)) * SMK + warp_m + 8 * ((lane >> 3) & 1)
        : (warp_m + (lane & 7) + 8 * ((lane >> 3) & 1)) * SMJ + 8 * (lane >> 4);
    const int boff = TRB
        ? ((lane & 7) + 8 * ((lane >> 3) & 1)) * SMK + warp_n + 8 * (lane >> 4)
        : (warp_n + (lane & 7) + 8 * (lane >> 4)) * SMJ + 8 * ((lane >> 3) & 1);
    const uint32_t aBase0 = smem_u32(&Asm[aoff]);
    const uint32_t bBase0 = smem_u32(&Bsm[boff]);

    float acc[4][4][4] = {};
    const int KT = K >> 6;    // 64 halves per k-tile

    auto load_stage = [&](int st, int kt) {
        const int k0 = kt * 64;
        __half* As = Asm + st * AH;
        __half* Bs = Bsm + st * BH;
        #pragma unroll
        for (int i = 0; i < 4; i++) {
            int chunk = tid + i * 256;                  // 1024 chunks of 8 halves
            if (TRA == 0) {
                int row = chunk >> 3, c = (chunk & 7) * 8;
                cp16(&As[row * SMJ + c], A + (long long)row * lda + k0 + c);
            } else {
                int row = chunk >> 4, c = (chunk & 15) * 8;
                cp16(&As[row * SMK + c], A + (long long)(k0 + row) * lda + c);
            }
            if (TRB == 0) {
                int row = chunk >> 3, c = (chunk & 7) * 8;
                cp16(&Bs[row * SMJ + c], B + (long long)row * ldb + k0 + c);
            } else {
                int row = chunk >> 4, c = (chunk & 15) * 8;
                cp16(&Bs[row * SMK + c], B + (long long)(k0 + row) * ldb + c);
            }
        }
        asm volatile("cp.async.commit_group;" ::: "memory");
    };

    // prologue: stages 0,1
    load_stage(0, 0);
    if (KT > 1) load_stage(1, 1);

    int sc = 0, sl = 2;
    for (int kt = 0; kt < KT; kt++) {
        if (kt + 1 < KT) asm volatile("cp.async.wait_group 1;" ::: "memory");
        else             asm volatile("cp.async.wait_group 0;" ::: "memory");
        __syncthreads();

        if (kt + 2 < KT) load_stage(sl, kt + 2);

        const uint32_t aB = aBase0 + sc * AH * 2;
        const uint32_t bB = bBase0 + sc * BH * 2;
        #pragma unroll
        for (int ks = 0; ks < 4; ks++) {
            uint32_t afr[4][4], bfr[4][2], btmp[4];
            #pragma unroll
            for (int mb = 0; mb < 4; mb++) {
                if (TRA) ldsm4t(afr[mb], aB + (ks * 16 * SMK + mb * 16) * 2);
                else     ldsm4 (afr[mb], aB + (mb * 16 * SMJ + ks * 16) * 2);
            }
            #pragma unroll
            for (int h = 0; h < 2; h++) {
                if (TRB) ldsm4t(btmp, bB + (ks * 16 * SMK + h * 16) * 2);
                else     ldsm4 (btmp, bB + (h * 16 * SMJ + ks * 16) * 2);
                bfr[2 * h][0]     = btmp[0]; bfr[2 * h][1]     = btmp[1];
                bfr[2 * h + 1][0] = btmp[2]; bfr[2 * h + 1][1] = btmp[3];
            }
            #pragma unroll
            for (int mb = 0; mb < 4; mb++)
                #pragma unroll
                for (int nb = 0; nb < 4; nb++)
                    mma16816(acc[mb][nb], afr[mb], bfr[nb]);
        }
        sc = (sc == 2) ? 0 : sc + 1;
        sl = (sl == 2) ? 0 : sl + 1;
    }

    const float alpha = alpha_ptr ? *alpha_ptr : 1.0f;
    OUT* C = Cg + (long long)blockIdx.z * sC + (long long)blockIdx.y * 128 * ldc
           + (long long)blockIdx.x * 128;
    const int colbase = blockIdx.x * 128;
    #pragma unroll
    for (int mb = 0; mb < 4; mb++) {
        const int row = warp_m + mb * 16 + gid;
        #pragma unroll
        for (int nb = 0; nb < 4; nb++) {
            const int col = warp_n + nb * 8 + 2 * t4;
            float bx = 0.0f, by = 0.0f;
            if (bias) { bx = bias[colbase + col]; by = bias[colbase + col + 1]; }
            store2(&C[(long long)row * ldc + col],
                   acc[mb][nb][0] * alpha + bx, acc[mb][nb][1] * alpha + by);
            store2(&C[(long long)(row + 8) * ldc + col],
                   acc[mb][nb][2] * alpha + bx, acc[mb][nb][3] * alpha + by);
        }
    }
}

// ---------------------------------------------------------------------------
// float -> half bulk convert
// ---------------------------------------------------------------------------
__global__ void f2h_kernel(const float* __restrict__ in, __half* __restrict__ out, int n4) {
    int i = blockIdx.x * blockDim.x + threadIdx.x;
    if (i < n4) {
        float4 v = reinterpret_cast<const float4*>(in)[i];
        __half2* o = reinterpret_cast<__half2*>(out);
        o[2 * i]     = __floats2half2_rn(v.x, v.y);
        o[2 * i + 1] = __floats2half2_rn(v.z, v.w);
    }
}

// ---------------------------------------------------------------------------
// Block reduction helpers (256 threads): shuffle + 8-entry smem broadcast
// ---------------------------------------------------------------------------
__device__ __forceinline__ float blk_sum256(float v, float* ws, int tid) {
    #pragma unroll
    for (int o = 16; o > 0; o >>= 1) v += __shfl_xor_sync(0xFFFFFFFFu, v, o);
    if ((tid & 31) == 0) ws[tid >> 5] = v;
    __syncthreads();
    float t = ws[0];
    #pragma unroll
    for (int i = 1; i < 8; i++) t += ws[i];
    return t;
}
__device__ __forceinline__ float blk_max256(float v, float* ws, int tid) {
    #pragma unroll
    for (int o = 16; o > 0; o >>= 1) v = fmaxf(v, __shfl_xor_sync(0xFFFFFFFFu, v, o));
    if ((tid & 31) == 0) ws[tid >> 5] = v;
    __syncthreads();
    float t = ws[0];
    #pragma unroll
    for (int i = 1; i < 8; i++) t = fmaxf(t, ws[i]);
    return t;
}

// ---------------------------------------------------------------------------
// claw mean, two-phase: 144 partial blocks then 1 finalize block
// ---------------------------------------------------------------------------
__global__ void claw_part_kernel(const float* __restrict__ claw) {
    __shared__ float ws[8];
    const int tid = threadIdx.x;
    const float* p = claw + (long long)blockIdx.x * 4096;
    float s = 0.0f;
    #pragma unroll
    for (int i = 0; i < 4; i++) {
        float4 v = reinterpret_cast<const float4*>(p)[tid + i * 256];
        s += v.x + v.y + v.z + v.w;
    }
    s = blk_sum256(s, ws, tid);
    if (tid == 0) g_part[blockIdx.x] = s;
}
__global__ void claw_fin_kernel() {
    __shared__ float ws[8];
    const int tid = threadIdx.x;
    float s = (tid < 144) ? g_part[tid] : 0.0f;
    s = blk_sum256(s, ws, tid);
    if (tid == 0) g_scale = (s / (float)(DIM * DIM)) * TEMP_INV;
}

// ---------------------------------------------------------------------------
// LayerNorm (+ReLU), last dim 768. One block (256) per row. IN in, OUT out.
// ---------------------------------------------------------------------------
template <typename IN, typename OUT>
__global__ void ln_relu_kernel(const IN* __restrict__ X, OUT* __restrict__ Y,
                               const float* __restrict__ g, const float* __restrict__ beta) {
    __shared__ float ws1[8], ws2[8];
    const int tid = threadIdx.x;
    const IN* x = X + (long long)blockIdx.x * DIM;
    OUT*      y = Y + (long long)blockIdx.x * DIM;

    float v0 = (float)x[tid], v1 = (float)x[tid + 256], v2 = (float)x[tid + 512];
    const float m = blk_sum256(v0 + v1 + v2, ws1, tid) * (1.0f / DIM);
    float d0 = v0 - m, d1 = v1 - m, d2 = v2 - m;
    const float var = blk_sum256(d0 * d0 + d1 * d1 + d2 * d2, ws2, tid) * (1.0f / DIM);
    const float rs = rsqrtf(var + 1e-5f);
    y[tid]       = (OUT)fmaxf(0.0f, d0 * rs * g[tid]       + beta[tid]);
    y[tid + 256] = (OUT)fmaxf(0.0f, d1 * rs * g[tid + 256] + beta[tid + 256]);
    y[tid + 512] = (OUT)fmaxf(0.0f, d2 * rs * g[tid + 512] + beta[tid + 512]);
}

// ---------------------------------------------------------------------------
// Row softmax over 2048, half, in place. One block (256) per row.
// ---------------------------------------------------------------------------
__global__ void softmax_h_kernel(__half* __restrict__ X) {
    __shared__ float ws1[8], ws2[8];
    const int tid = threadIdx.x;
    __half2* x = reinterpret_cast<__half2*>(X + (long long)blockIdx.x * SEQ);

    float2 v[4];
    #pragma unroll
    for (int i = 0; i < 4; i++) v[i] = __half22float2(x[tid * 4 + i]);

    float mx = v[0].x;
    #pragma unroll
    for (int i = 0; i < 4; i++) mx = fmaxf(mx, fmaxf(v[i].x, v[i].y));
    mx = blk_max256(mx, ws1, tid);

    float sum = 0.0f;
    #pragma unroll
    for (int i = 0; i < 4; i++) {
        v[i].x = expf(v[i].x - mx); v[i].y = expf(v[i].y - mx);
        sum += v[i].x + v[i].y;
    }
    sum = blk_sum256(sum, ws2, tid);
    const float inv = 1.0f / sum;
    #pragma unroll
    for (int i = 0; i < 4; i++)
        x[tid * 4 + i] = __floats2half2_rn(v[i].x * inv, v[i].y * inv);
}

// ---------------------------------------------------------------------------
// Launch
// ---------------------------------------------------------------------------
extern "C" void kernel_launch(void* const* d_in, const int* in_sizes, int n_in,
                              void* d_out, int out_size) {
    const float* vis   = (const float*)d_in[0];
    const float* lang  = (const float*)d_in[1];
    const float* vW    = (const float*)d_in[2];
    const float* vb    = (const float*)d_in[3];
    const float* vg    = (const float*)d_in[4];
    const float* vbeta = (const float*)d_in[5];
    const float* lW    = (const float*)d_in[6];
    const float* lb    = (const float*)d_in[7];
    const float* lg    = (const float*)d_in[8];
    const float* lbeta = (const float*)d_in[9];
    const float* claw  = (const float*)d_in[10];
    const float* oW    = (const float*)d_in[11];
    const float* ob    = (const float*)d_in[12];
    const float* og    = (const float*)d_in[13];
    const float* obeta = (const float*)d_in[14];
    float* out = (float*)d_out;

    float  *scale;
    __half *visH, *langH, *vpH, *lpH, *AmH, *combH, *vWH, *lWH, *oWH;
    cudaGetSymbolAddress((void**)&visH,  g_visH);
    cudaGetSymbolAddress((void**)&langH, g_langH);
    cudaGetSymbolAddress((void**)&vpH,   g_vpH);
    cudaGetSymbolAddress((void**)&lpH,   g_lpH);
    cudaGetSymbolAddress((void**)&AmH,   g_AmH);
    cudaGetSymbolAddress((void**)&combH, g_combH);
    cudaGetSymbolAddress((void**)&vWH,   g_vWH);
    cudaGetSymbolAddress((void**)&lWH,   g_lWH);
    cudaGetSymbolAddress((void**)&oWH,   g_oWH);
    cudaGetSymbolAddress((void**)&scale, g_scale);

    // half scratch reuse: proj tmps live in combH until LN consumes them;
    // out_pre tmp lives in visH (free after proj GEMM 1).
    __half* tmpH0 = combH;
    __half* tmpH1 = combH + (size_t)ROWS * DIM;
    __half* outH  = visH;

    const long long SD = (long long)SEQ * DIM;
    const long long SS = (long long)SEQ * SEQ;
    const long long SC = (long long)SEQ * 2 * DIM;
    const int N4  = ROWS * DIM / 4;
    const int W4  = DIM * DIM / 4;
    const int OW4 = 2 * DIM * DIM / 4;

    constexpr int SM01 = GemmSmem<0, 1>::BYTES;
    constexpr int SM00 = GemmSmem<0, 0>::BYTES;
    constexpr int SM11 = GemmSmem<1, 1>::BYTES;
    cudaFuncSetAttribute(h_gemm<0, 1, __half>, cudaFuncAttributeMaxDynamicSharedMemorySize, SM01);
    cudaFuncSetAttribute(h_gemm<0, 0, __half>, cudaFuncAttributeMaxDynamicSharedMemorySize, SM00);
    cudaFuncSetAttribute(h_gemm<1, 1, __half>, cudaFuncAttributeMaxDynamicSharedMemorySize, SM11);

    claw_part_kernel<<<144, 256>>>(claw);
    claw_fin_kernel<<<1, 256>>>();

    f2h_kernel<<<(N4 + 255) / 256, 256>>>(vis,  visH,  N4);
    f2h_kernel<<<(N4 + 255) / 256, 256>>>(lang, langH, N4);
    f2h_kernel<<<(W4 + 255) / 256, 256>>>(vW, vWH, W4);
    f2h_kernel<<<(W4 + 255) / 256, 256>>>(lW, lWH, W4);
    f2h_kernel<<<(OW4 + 255) / 256, 256>>>(oW, oWH, OW4);

    // proj GEMMs -> half tmp
    h_gemm<0, 1, __half><<<dim3(DIM / 128, ROWS / 128, 1), 256, SM01>>>(
        visH, vWH, tmpH0, DIM, DIM, DIM, DIM, 0, 0, 0, nullptr, vb);
    h_gemm<0, 1, __half><<<dim3(DIM / 128, ROWS / 128, 1), 256, SM01>>>(
        langH, lWH, tmpH1, DIM, DIM, DIM, DIM, 0, 0, 0, nullptr, lb);

    // LN + ReLU -> half projections
    ln_relu_kernel<__half, __half><<<ROWS, 256>>>(tmpH0, vpH, vg, vbeta);
    ln_relu_kernel<__half, __half><<<ROWS, 256>>>(tmpH1, lpH, lg, lbeta);

    // sim = (vp @ lp^T) * scale -> half
    h_gemm<0, 0, __half><<<dim3(SEQ / 128, SEQ / 128, BATCH), 256, SM00>>>(
        vpH, lpH, AmH, DIM, DIM, SEQ, DIM, SD, SD, SS, scale, nullptr);

    softmax_h_kernel<<<BATCH * SEQ, 256>>>(AmH);

    // aligned_vision = A @ vp  -> combH[:, :768]   (overwrites tmp region; tmps consumed)
    h_gemm<0, 1, __half><<<dim3(DIM / 128, SEQ / 128, BATCH), 256, SM01>>>(
        AmH, vpH, combH, SEQ, DIM, 2 * DIM, SEQ, SS, SD, SC, nullptr, nullptr);

    // aligned_language = A^T @ lp -> combH[:, 768:]
    h_gemm<1, 1, __half><<<dim3(DIM / 128, SEQ / 128, BATCH), 256, SM11>>>(
        AmH, lpH, combH + DIM, SEQ, DIM, 2 * DIM, SEQ, SS, SD, SC, nullptr, nullptr);

    // out_pre = comb @ oW + ob -> half (visH scratch)
    h_gemm<0, 1, __half><<<dim3(DIM / 128, ROWS / 128, 1), 256, SM01>>>(
        combH, oWH, outH, 2 * DIM, DIM, DIM, 2 * DIM, 0, 0, 0, nullptr, ob);

    // final LN + ReLU -> f32 out
    ln_relu_kernel<__half, float><<<ROWS, 256>>>(outH, out, og, obeta);
}